// round 12
// baseline (speedup 1.0000x reference)
#include <cuda_runtime.h>
#include <cuda_bf16.h>
#include <math.h>
#include <stdint.h>

#define NUM_L   4096
#define NTOT    8192
#define CC      768
#define HH      12
#define DDIM    64
#define KSEL    8
#define PPAT    256
#define NLAYERS 4
#define NEG_SLOPE 0.2f

// ---------------- device scratch ----------------
__device__ float g_sim[NUM_L * NUM_L];          // 64 MB
__device__ int   g_idx[NUM_L * KSEL];
__device__ float g_z [NTOT * CC];
__device__ float g_el[NTOT * HH];
__device__ float g_er[NTOT * HH];
// double-buffered x (hi/lo): GEMM reads buf[cur], writes identity rows to buf[1-cur]
__device__ __nv_bfloat16 g_xbh[2][NTOT * CC], g_xbl[2][NTOT * CC];
__device__ __nv_bfloat16 g_LRh[NTOT * CC], g_LRl[NTOT * CC];
__device__ __nv_bfloat16 g_Wgt_h[CC * CC], g_Wgt_l[CC * CC];
__device__ __nv_bfloat16 g_Wst_h[NLAYERS * CC * CC], g_Wst_l[NLAYERS * CC * CC];
__device__ int   g_deg[NUM_L];
__device__ int   g_off[NUM_L + 1];
__device__ int   g_elist[NUM_L * KSEL];

__device__ __forceinline__ float lrelu(float x) { return x >= 0.f ? x : NEG_SLOPE * x; }

__device__ __forceinline__ uint32_t smem_u32(const void* p) {
    uint32_t a;
    asm("{ .reg .u64 t; cvta.to.shared.u64 t, %1; cvt.u32.u64 %0, t; }" : "=r"(a) : "l"(p));
    return a;
}
__device__ __forceinline__ void split2(float v, __nv_bfloat16& h, __nv_bfloat16& l) {
    h = __float2bfloat16(v);
    l = __float2bfloat16(v - __bfloat162float(h));
}

// ======================= mma.sync bf16 GEMM =======================
// C = A*B^T; A,B bf16 (hi,lo) pairs, K-contiguous. NMMA=3: full split precision,
// NMMA=1: hi*hi only (2 smem tiles -> NST=4 fits the same smem budget).
// Fused epilogues (optional): el/er head-dots (as_/ad_); bias+ELU+split x-out.
#define SA      40
#define TILE_B  (128 * SA * 2)          // 10240 B per 128x32 tile
#define GEMM_SMEM 81920                 // 2 stages x 4 tiles == 4 stages x 2 tiles

#define CP16(s, g) \
    asm volatile("cp.async.cg.shared.global [%0], [%1], 16;" :: "r"(s), "l"(g))
#define CP_COMMIT() asm volatile("cp.async.commit_group;" ::: "memory")

#define LDSM4(r0, r1, r2, r3, a) \
    asm volatile("ldmatrix.sync.aligned.m8n8.x4.shared.b16 {%0,%1,%2,%3}, [%4];" \
                 : "=r"(r0), "=r"(r1), "=r"(r2), "=r"(r3) : "r"(a))

#define MMA16816(d, a, b) \
    asm volatile("mma.sync.aligned.m16n8k16.row.col.f32.bf16.bf16.f32 " \
                 "{%0,%1,%2,%3},{%4,%5,%6,%7},{%8,%9},{%0,%1,%2,%3};" \
                 : "+f"((d)[0]), "+f"((d)[1]), "+f"((d)[2]), "+f"((d)[3]) \
                 : "r"((a)[0]), "r"((a)[1]), "r"((a)[2]), "r"((a)[3]), \
                   "r"((b)[0]), "r"((b)[1]))

template<int NMMA, int NST>
__global__ void __launch_bounds__(256, 2) gemm_mma(
    const __nv_bfloat16* __restrict__ Ah, const __nv_bfloat16* __restrict__ Al,
    const __nv_bfloat16* __restrict__ Bh, const __nv_bfloat16* __restrict__ Bl,
    float* __restrict__ Cf, __nv_bfloat16* __restrict__ Ch, __nv_bfloat16* __restrict__ Cl,
    const float* __restrict__ as_, const float* __restrict__ ad_,
    const float* __restrict__ bias, __nv_bfloat16* __restrict__ xh,
    __nv_bfloat16* __restrict__ xl, int elu,
    int M, int N, int K, int splitout)
{
    extern __shared__ __align__(16) char dsm[];
    __shared__ float s_red[128][2][2];
    const int NTILES = (NMMA == 1) ? 2 : 4;
    const int STB = NTILES * TILE_B;
    const uint32_t sbase = smem_u32(dsm);
    const int tid = threadIdx.x;
    const int wid = tid >> 5, lane = tid & 31;
    const int wm = wid & 1, wn = wid >> 1;
    const int bm = blockIdx.y * 128, bn = blockIdx.x * 128;

    const __nv_bfloat16* srcs[4] = {
        Ah + (size_t)bm * K, Al + (size_t)bm * K,
        Bh + (size_t)bn * K, Bl + (size_t)bn * K };

    const int r0 = tid >> 2, c0 = tid & 3;
    const int r1 = (tid + 256) >> 2, c1 = (tid + 256) & 3;

    const int lj = lane >> 3, lr = lane & 7;
    const uint32_t aoff = (uint32_t)((((lj & 1) * 8 + lr) * SA + (lj >> 1) * 8) * 2);
    const uint32_t boff = (uint32_t)((((lj >> 1) * 8 + lr) * SA + (lj & 1) * 8) * 2);

    float acc[4][4][4];
#pragma unroll
    for (int i = 0; i < 4; i++)
#pragma unroll
        for (int j = 0; j < 4; j++)
#pragma unroll
            for (int k = 0; k < 4; k++) acc[i][j][k] = 0.f;

    const int nc = K >> 5;
    const int NPRO = (NST == 2) ? 2 : (NST - 1);

#pragma unroll
    for (int s = 0; s < NPRO; s++) {
        const uint32_t st = sbase + s * STB;
        const int kb = s * 32;
#pragma unroll
        for (int t = 0; t < 4; t++) {
            if (NMMA == 1 && (t & 1)) continue;
            const int slot = (NMMA == 1) ? (t >> 1) : t;
            const __nv_bfloat16* gp = srcs[t] + kb;
            CP16(st + slot * TILE_B + r0 * (SA * 2) + c0 * 16, gp + (size_t)r0 * K + c0 * 8);
            CP16(st + slot * TILE_B + r1 * (SA * 2) + c1 * 16, gp + (size_t)r1 * K + c1 * 8);
        }
        CP_COMMIT();
    }

    for (int c = 0; c < nc; c++) {
        asm volatile("cp.async.wait_group %0;" :: "n"(NST - 2) : "memory");
        __syncthreads();
        if (NST > 2) {
            // stage c+NST-1 -> buffer (c-1)%NST, freed by the sync above
            if (c + NST - 1 < nc) {
                const uint32_t st2 = sbase + ((c + NST - 1) % NST) * STB;
                const int kb = (c + NST - 1) * 32;
#pragma unroll
                for (int t = 0; t < 4; t++) {
                    if (NMMA == 1 && (t & 1)) continue;
                    const int slot = (NMMA == 1) ? (t >> 1) : t;
                    const __nv_bfloat16* gp = srcs[t] + kb;
                    CP16(st2 + slot * TILE_B + r0 * (SA * 2) + c0 * 16, gp + (size_t)r0 * K + c0 * 8);
                    CP16(st2 + slot * TILE_B + r1 * (SA * 2) + c1 * 16, gp + (size_t)r1 * K + c1 * 8);
                }
            }
            CP_COMMIT();
        }

        const uint32_t st = sbase + (c % NST) * STB;
        const uint32_t sAh = st + (uint32_t)(wm * 64 * SA * 2);
        const uint32_t sAl = st + 1 * TILE_B + (uint32_t)(wm * 64 * SA * 2);
        const uint32_t sBh = st + ((NMMA == 1) ? 1 : 2) * TILE_B + (uint32_t)(wn * 32 * SA * 2);
        const uint32_t sBl = st + 3 * TILE_B + (uint32_t)(wn * 32 * SA * 2);
#pragma unroll
        for (int kk = 0; kk < 2; kk++) {
            const uint32_t kadd = kk * 32;
            uint32_t bh[2][4], bl[2][4];
#pragma unroll
            for (int np = 0; np < 2; np++) {
                const uint32_t noff = (uint32_t)(np * 16 * SA * 2) + kadd;
                LDSM4(bh[np][0], bh[np][1], bh[np][2], bh[np][3], sBh + noff + boff);
                if (NMMA == 3)
                    LDSM4(bl[np][0], bl[np][1], bl[np][2], bl[np][3], sBl + noff + boff);
            }
#pragma unroll
            for (int mt = 0; mt < 4; mt++) {
                uint32_t ah[4], al[4];
                const uint32_t moff = (uint32_t)(mt * 16 * SA * 2) + kadd;
                LDSM4(ah[0], ah[1], ah[2], ah[3], sAh + moff + aoff);
                if (NMMA == 3)
                    LDSM4(al[0], al[1], al[2], al[3], sAl + moff + aoff);
#pragma unroll
                for (int nt = 0; nt < 4; nt++) {
                    const uint32_t* bhf = &bh[nt >> 1][(nt & 1) * 2];
                    MMA16816(acc[mt][nt], ah, bhf);
                    if (NMMA == 3) {
                        const uint32_t* blf = &bl[nt >> 1][(nt & 1) * 2];
                        MMA16816(acc[mt][nt], ah, blf);
                        MMA16816(acc[mt][nt], al, bhf);
                    }
                }
            }
        }
        if (NST == 2) {
            __syncthreads();
            if (c + 2 < nc) {
                const int kb = (c + 2) * 32;
#pragma unroll
                for (int t = 0; t < 4; t++) {
                    if (NMMA == 1 && (t & 1)) continue;
                    const int slot = (NMMA == 1) ? (t >> 1) : t;
                    const __nv_bfloat16* gp = srcs[t] + kb;
                    CP16(st + slot * TILE_B + r0 * (SA * 2) + c0 * 16, gp + (size_t)r0 * K + c0 * 8);
                    CP16(st + slot * TILE_B + r1 * (SA * 2) + c1 * 16, gp + (size_t)r1 * K + c1 * 8);
                }
            }
            CP_COMMIT();
        }
    }

    const int er = lane >> 2, ec = (lane & 3) * 2;

    // ---- C store (+ optional fused bias/ELU/split x-out into the NEXT buffer) ----
#pragma unroll
    for (int mt = 0; mt < 4; mt++) {
        const int row = bm + wm * 64 + mt * 16 + er;
#pragma unroll
        for (int nt = 0; nt < 4; nt++) {
            const int col = bn + wn * 32 + nt * 8 + ec;
            if (!splitout) {
                float2* p0 = (float2*)(Cf + (size_t)row * N + col);
                float2* p1 = (float2*)(Cf + (size_t)(row + 8) * N + col);
                *p0 = make_float2(acc[mt][nt][0], acc[mt][nt][1]);
                *p1 = make_float2(acc[mt][nt][2], acc[mt][nt][3]);
                if (xh != nullptr) {
                    const float b0 = bias[col], b1 = bias[col + 1];
#pragma unroll
                    for (int half = 0; half < 2; half++) {
                        float v0 = acc[mt][nt][half * 2 + 0] + b0;
                        float v1 = acc[mt][nt][half * 2 + 1] + b1;
                        if (elu) {
                            v0 = v0 > 0.f ? v0 : expm1f(v0);
                            v1 = v1 > 0.f ? v1 : expm1f(v1);
                        }
                        __nv_bfloat16 h0, l0, h1, l1;
                        split2(v0, h0, l0); split2(v1, h1, l1);
                        const size_t o = (size_t)(row + half * 8) * N + col;
                        __nv_bfloat162 hv; hv.x = h0; hv.y = h1;
                        __nv_bfloat162 lv2; lv2.x = l0; lv2.y = l1;
                        *(__nv_bfloat162*)(xh + o) = hv;
                        *(__nv_bfloat162*)(xl + o) = lv2;
                    }
                }
            } else {
#pragma unroll
                for (int half = 0; half < 2; half++) {
                    const size_t o = (size_t)(row + half * 8) * N + col;
                    __nv_bfloat16 h0, l0, h1, l1;
                    split2(acc[mt][nt][half * 2 + 0], h0, l0);
                    split2(acc[mt][nt][half * 2 + 1], h1, l1);
                    __nv_bfloat162 hv; hv.x = h0; hv.y = h1;
                    __nv_bfloat162 lv2; lv2.x = l0; lv2.y = l1;
                    *(__nv_bfloat162*)(Ch + o) = hv;
                    *(__nv_bfloat162*)(Cl + o) = lv2;
                }
            }
        }
    }

    // ---- fused el/er epilogue (layer GEMMs; N == 768, heads of 64 cols) ----
    if (as_ != nullptr) {
        const int h    = (bn + wn * 32) >> 6;
        const int hl   = wn >> 1;
        const int cih0 = (wn & 1) * 32;
        float elv[4][2], erv[4][2];
#pragma unroll
        for (int mt = 0; mt < 4; mt++) { elv[mt][0] = elv[mt][1] = erv[mt][0] = erv[mt][1] = 0.f; }
#pragma unroll
        for (int nt = 0; nt < 4; nt++) {
            const int cih = cih0 + nt * 8 + ec;
            const float a0 = as_[h * DDIM + cih], a1 = as_[h * DDIM + cih + 1];
            const float d0 = ad_[h * DDIM + cih], d1 = ad_[h * DDIM + cih + 1];
#pragma unroll
            for (int mt = 0; mt < 4; mt++) {
                elv[mt][0] += acc[mt][nt][0] * a0 + acc[mt][nt][1] * a1;
                elv[mt][1] += acc[mt][nt][2] * a0 + acc[mt][nt][3] * a1;
                erv[mt][0] += acc[mt][nt][0] * d0 + acc[mt][nt][1] * d1;
                erv[mt][1] += acc[mt][nt][2] * d0 + acc[mt][nt][3] * d1;
            }
        }
#pragma unroll
        for (int mt = 0; mt < 4; mt++)
#pragma unroll
            for (int hf = 0; hf < 2; hf++) {
#pragma unroll
                for (int o = 1; o <= 2; o <<= 1) {
                    elv[mt][hf] += __shfl_xor_sync(0xffffffffu, elv[mt][hf], o);
                    erv[mt][hf] += __shfl_xor_sync(0xffffffffu, erv[mt][hf], o);
                }
            }
        __syncthreads();
        if ((wn & 1) == 0 && (lane & 3) == 0) {
#pragma unroll
            for (int mt = 0; mt < 4; mt++)
#pragma unroll
                for (int hf = 0; hf < 2; hf++) {
                    const int r = wm * 64 + mt * 16 + er + hf * 8;
                    s_red[r][hl][0] = elv[mt][hf];
                    s_red[r][hl][1] = erv[mt][hf];
                }
        }
        __syncthreads();
        if ((wn & 1) == 1 && (lane & 3) == 0) {
#pragma unroll
            for (int mt = 0; mt < 4; mt++)
#pragma unroll
                for (int hf = 0; hf < 2; hf++) {
                    const int r = wm * 64 + mt * 16 + er + hf * 8;
                    g_el[(size_t)(bm + r) * HH + h] = s_red[r][hl][0] + elv[mt][hf];
                    g_er[(size_t)(bm + r) * HH + h] = s_red[r][hl][1] + erv[mt][hf];
                }
        }
    }
}

// ---------------- batched 768x768 transpose + split ----------------
__global__ void transpose_split_all(const float* __restrict__ Wg,
                                    const float* __restrict__ Ws,
                                    __nv_bfloat16* __restrict__ WgH, __nv_bfloat16* __restrict__ WgL,
                                    __nv_bfloat16* __restrict__ WsH, __nv_bfloat16* __restrict__ WsL) {
    __shared__ float t[32][33];
    int zi = blockIdx.z;
    const float* src = (zi == 0) ? Wg : Ws + (size_t)(zi - 1) * CC * CC;
    __nv_bfloat16* dh = (zi == 0) ? WgH : WsH + (size_t)(zi - 1) * CC * CC;
    __nv_bfloat16* dl = (zi == 0) ? WgL : WsL + (size_t)(zi - 1) * CC * CC;
    int bx = blockIdx.x * 32, by = blockIdx.y * 32;
    int x = bx + threadIdx.x;
#pragma unroll
    for (int j = 0; j < 32; j += 8)
        t[threadIdx.y + j][threadIdx.x] = src[(size_t)(by + threadIdx.y + j) * CC + x];
    __syncthreads();
    int x2 = by + threadIdx.x;
#pragma unroll
    for (int j = 0; j < 32; j += 8) {
        float v = t[threadIdx.x][threadIdx.y + j];
        size_t o = (size_t)(bx + threadIdx.y + j) * CC + x2;
        __nv_bfloat16 h, l; split2(v, h, l);
        dh[o] = h; dl[o] = l;
    }
}

// ---------------- top-16 candidates + fp32 rescore + exact top-8 ----------------
__global__ __launch_bounds__(256) void topk_rescore_kernel() {
    __shared__ float sv[NUM_L];
    __shared__ float rv[256];
    __shared__ int   ri[256];
    __shared__ int   cand[16];
    __shared__ float cs[16];
    __shared__ float lrow[CC];
    int r = blockIdx.x, tid = threadIdx.x;
    const float* row = g_sim + (size_t)r * NUM_L;
    for (int c = tid; c < NUM_L; c += 256) sv[c] = row[c];
    __syncthreads();
    for (int t = 0; t < 16; t++) {
        float bv = -INFINITY; int bi = NUM_L;
        for (int c = tid; c < NUM_L; c += 256) {
            float v = sv[c];
            if (v > bv || (v == bv && c < bi)) { bv = v; bi = c; }
        }
        rv[tid] = bv; ri[tid] = bi;
        __syncthreads();
        for (int s = 128; s > 0; s >>= 1) {
            if (tid < s) {
                float v = rv[tid + s]; int i2 = ri[tid + s];
                if (v > rv[tid] || (v == rv[tid] && i2 < ri[tid])) { rv[tid] = v; ri[tid] = i2; }
            }
            __syncthreads();
        }
        if (tid == 0) { cand[t] = ri[0]; sv[ri[0]] = -INFINITY; }
        __syncthreads();
    }
    for (int d = tid; d < CC; d += 256)
        lrow[d] = __bfloat162float(g_LRh[(size_t)r * CC + d])
                + __bfloat162float(g_LRl[(size_t)r * CC + d]);
    __syncthreads();
    int wid = tid >> 5, lane = tid & 31;
    for (int c = wid; c < 16; c += 8) {
        size_t rr = (size_t)(cand[c] + NUM_L) * CC;
        float s = 0.f;
        for (int d = lane; d < CC; d += 32)
            s += lrow[d] * (__bfloat162float(g_LRh[rr + d]) + __bfloat162float(g_LRl[rr + d]));
#pragma unroll
        for (int o = 16; o; o >>= 1) s += __shfl_xor_sync(0xffffffffu, s, o);
        if (lane == 0) cs[c] = s;
    }
    __syncthreads();
    if (tid == 0) {
        unsigned used = 0;
        for (int t = 0; t < KSEL; t++) {
            float bv = -INFINITY; int bslot = 0, bidx = NUM_L;
            for (int c = 0; c < 16; c++) {
                if (used & (1u << c)) continue;
                if (cs[c] > bv || (cs[c] == bv && cand[c] < bidx)) {
                    bv = cs[c]; bidx = cand[c]; bslot = c;
                }
            }
            used |= 1u << bslot;
            g_idx[r * KSEL + t] = bidx;
        }
    }
}

// ---------------- CSR build ----------------
__global__ void zero_deg_kernel() {
    int i = blockIdx.x * 256 + threadIdx.x;
    if (i < NUM_L) g_deg[i] = 0;
}
__global__ void count_deg_kernel() {
    int e = blockIdx.x * 256 + threadIdx.x;
    if (e < NUM_L * KSEL) atomicAdd(&g_deg[g_idx[e]], 1);
}
__global__ __launch_bounds__(512) void scan_off_kernel() {
    __shared__ int ss[512];
    int tid = threadIdx.x;
    int base = tid * 8;
    int loc[8]; int s = 0;
#pragma unroll
    for (int i = 0; i < 8; i++) { loc[i] = s; s += g_deg[base + i]; }
    ss[tid] = s; __syncthreads();
    for (int d = 1; d < 512; d <<= 1) {
        int v = (tid >= d) ? ss[tid - d] : 0;
        __syncthreads();
        ss[tid] += v;
        __syncthreads();
    }
    int excl = ss[tid] - s;
#pragma unroll
    for (int i = 0; i < 8; i++) g_off[base + i] = excl + loc[i];
    if (tid == 511) g_off[NUM_L] = ss[511];
}
__global__ void init_cursor_kernel() {
    int i = blockIdx.x * 256 + threadIdx.x;
    if (i < NUM_L) g_deg[i] = g_off[i];
}
__global__ void fill_atomic_kernel() {
    int e = blockIdx.x * 256 + threadIdx.x;
    if (e < NUM_L * KSEL) {
        int pos = atomicAdd(&g_deg[g_idx[e]], 1);
        g_elist[pos] = e;
    }
}
__global__ void sort_convert_kernel() {
    int j = blockIdx.x * 256 + threadIdx.x;
    if (j >= NUM_L) return;
    int e0 = g_off[j], e1 = g_off[j + 1];
    for (int i = e0 + 1; i < e1; i++) {
        int key = g_elist[i];
        int k = i - 1;
        while (k >= e0 && g_elist[k] > key) { g_elist[k + 1] = g_elist[k]; k--; }
        g_elist[k + 1] = key;
    }
    for (int i = e0; i < e1; i++) g_elist[i] >>= 3;
}

// ---------------- x init (buffer 0) ----------------
__global__ void init_x_kernel(const float* __restrict__ l, const float* __restrict__ r) {
    int i = blockIdx.x * 256 + threadIdx.x;
    if (i < NUM_L * CC) {
        split2(l[i], g_xbh[0][i], g_xbl[0][i]);
        split2(r[i], g_xbh[0][NUM_L * CC + i], g_xbl[0][NUM_L * CC + i]);
    }
}

// ---------------- fused bias + act + split ----------------
__device__ __forceinline__ void store_x(__nv_bfloat16* xh, __nv_bfloat16* xl,
                                        int n, int d, float v, int elu) {
    if (elu) v = v > 0.f ? v : expm1f(v);
    size_t o = (size_t)n * CC + d;
    split2(v, xh[o], xl[o]);
}

// ---------------- 12-channel block reductions ----------------
__device__ __forceinline__ void block_max12(float* lv, float* red, float* outp, int tid) {
#pragma unroll
    for (int h = 0; h < HH; h++)
#pragma unroll
        for (int o = 16; o; o >>= 1)
            lv[h] = fmaxf(lv[h], __shfl_xor_sync(0xffffffffu, lv[h], o));
    if ((tid & 31) == 0)
#pragma unroll
        for (int h = 0; h < HH; h++) red[(tid >> 5) * HH + h] = lv[h];
    __syncthreads();
    if (tid < HH) {
        float v = red[tid];
#pragma unroll
        for (int w = 1; w < 8; w++) v = fmaxf(v, red[w * HH + tid]);
        outp[tid] = v;
    }
    __syncthreads();
}
__device__ __forceinline__ void block_sum12(float* lv, float* red, float* outp, int tid) {
#pragma unroll
    for (int h = 0; h < HH; h++)
#pragma unroll
        for (int o = 16; o; o >>= 1)
            lv[h] += __shfl_xor_sync(0xffffffffu, lv[h], o);
    if ((tid & 31) == 0)
#pragma unroll
        for (int h = 0; h < HH; h++) red[(tid >> 5) * HH + h] = lv[h];
    __syncthreads();
    if (tid < HH) {
        float v = red[tid];
#pragma unroll
        for (int w = 1; w < 8; w++) v += red[w * HH + tid];
        outp[tid] = v;
    }
    __syncthreads();
}

// ---------------- GAT aggregation + act, graph 1 (right nodes only) ------------
__global__ __launch_bounds__(256) void agg1_kernel(const float* __restrict__ bias, int elu,
                                                   __nv_bfloat16* __restrict__ xh,
                                                   __nv_bfloat16* __restrict__ xl) {
    int j = blockIdx.x;
    int n = NUM_L + j;
    int tid = threadIdx.x;
    __shared__ float s_er[HH], s_m[HH], s_sum[HH], s_inv[HH];
    __shared__ float red[8 * HH];
    int e0 = g_off[j], e1 = g_off[j + 1];
    int deg = e1 - e0;
    if (tid < HH) s_er[tid] = g_er[n * HH + tid];
    __syncthreads();

    float lv[HH];
#pragma unroll
    for (int h = 0; h < HH; h++) lv[h] = -INFINITY;
    for (int t = tid; t < deg + 1; t += 256) {
        int src = (t < deg) ? g_elist[e0 + t] : n;
        const float* elp = g_el + src * HH;
#pragma unroll
        for (int h = 0; h < HH; h++) lv[h] = fmaxf(lv[h], lrelu(elp[h] + s_er[h]));
    }
    block_max12(lv, red, s_m, tid);

#pragma unroll
    for (int h = 0; h < HH; h++) lv[h] = 0.f;
    for (int t = tid; t < deg + 1; t += 256) {
        int src = (t < deg) ? g_elist[e0 + t] : n;
        const float* elp = g_el + src * HH;
#pragma unroll
        for (int h = 0; h < HH; h++) lv[h] += expf(lrelu(elp[h] + s_er[h]) - s_m[h]);
    }
    block_sum12(lv, red, s_sum, tid);
    if (tid < HH) s_inv[tid] = 1.f / s_sum[tid];
    __syncthreads();

    for (int d = tid; d < CC; d += 256) {
        int h = d >> 6;
        float m = s_m[h], inv = s_inv[h], erh = s_er[h];
        float acc = expf(lrelu(g_el[n * HH + h] + erh) - m) * inv * g_z[(size_t)n * CC + d];
        for (int e = e0; e < e1; e++) {
            int src = g_elist[e];
            acc += expf(lrelu(g_el[src * HH + h] + erh) - m) * inv * g_z[(size_t)src * CC + d];
        }
        store_x(xh, xl, n, d, acc + bias[d], elu);
    }
}

// ---------------- GAT aggregation + act, graph 2 (image nodes only) ------------
__global__ __launch_bounds__(256) void agg2_kernel(const float* __restrict__ bias,
                                                   int elu, int final_, float* outp,
                                                   __nv_bfloat16* __restrict__ xh,
                                                   __nv_bfloat16* __restrict__ xl) {
    int n = blockIdx.x * PPAT;
    int tid = threadIdx.x;
    __shared__ float s_er[HH], s_m[HH], s_sum[HH], s_inv[HH];
    __shared__ float s_w[PPAT * HH];
    __shared__ float red[8 * HH];
    if (tid < HH) s_er[tid] = g_er[n * HH + tid];
    __syncthreads();

    int src = n + tid;
    float ev[HH];
    const float* elp = g_el + src * HH;
#pragma unroll
    for (int h = 0; h < HH; h++) ev[h] = lrelu(elp[h] + s_er[h]);

    float lv[HH];
#pragma unroll
    for (int h = 0; h < HH; h++) lv[h] = ev[h];
    block_max12(lv, red, s_m, tid);

    float mult = (tid == 0) ? 2.f : 1.f;   // duplicated self edge
    float ex[HH];
#pragma unroll
    for (int h = 0; h < HH; h++) { ex[h] = expf(ev[h] - s_m[h]) * mult; lv[h] = ex[h]; }
    block_sum12(lv, red, s_sum, tid);
    if (tid < HH) s_inv[tid] = 1.f / s_sum[tid];
    __syncthreads();
#pragma unroll
    for (int h = 0; h < HH; h++) s_w[tid * HH + h] = ex[h] * s_inv[h];
    __syncthreads();

    for (int d = tid; d < CC; d += 256) {
        int h = d >> 6;
        float acc = 0.f;
        for (int i = 0; i < PPAT; i++)
            acc += s_w[i * HH + h] * g_z[(size_t)(n + i) * CC + d];
        float v = acc + bias[d];
        if (final_) {
            if (elu) v = v > 0.f ? v : expm1f(v);
            outp[(size_t)blockIdx.x * CC + d] = v;
        } else {
            store_x(xh, xl, n, d, v, elu);
        }
    }
}

// ---------------- launch ----------------
extern "C" void kernel_launch(void* const* d_in, const int* in_sizes, int n_in,
                              void* d_out, int out_size) {
    (void)in_sizes; (void)n_in; (void)out_size;
    const float* l_feat = (const float*)d_in[0];
    const float* r_feat = (const float*)d_in[1];
    const float* Wg     = (const float*)d_in[2];
    const float* Ws     = (const float*)d_in[3];
    const float* a_src  = (const float*)d_in[4];
    const float* a_dst  = (const float*)d_in[5];
    const float* b      = (const float*)d_in[6];
    float* out = (float*)d_out;

    cudaFuncSetAttribute(gemm_mma<3, 2>, cudaFuncAttributeMaxDynamicSharedMemorySize, GEMM_SMEM);
    cudaFuncSetAttribute(gemm_mma<1, 4>, cudaFuncAttributeMaxDynamicSharedMemorySize, GEMM_SMEM);

    __nv_bfloat16 *pWgh, *pWgl, *pWsh, *pWsl, *pLRh, *pLRl;
    __nv_bfloat16 *pXh[2], *pXl[2];
    float *pSim, *pZ;
    cudaGetSymbolAddress((void**)&pWgh, g_Wgt_h);
    cudaGetSymbolAddress((void**)&pWgl, g_Wgt_l);
    cudaGetSymbolAddress((void**)&pWsh, g_Wst_h);
    cudaGetSymbolAddress((void**)&pWsl, g_Wst_l);
    cudaGetSymbolAddress((void**)&pXh[0], g_xbh);
    cudaGetSymbolAddress((void**)&pXl[0], g_xbl);
    pXh[1] = pXh[0] + (size_t)NTOT * CC;
    pXl[1] = pXl[0] + (size_t)NTOT * CC;
    cudaGetSymbolAddress((void**)&pLRh, g_LRh);
    cudaGetSymbolAddress((void**)&pLRl, g_LRl);
    cudaGetSymbolAddress((void**)&pSim, g_sim);
    cudaGetSymbolAddress((void**)&pZ,   g_z);

    transpose_split_all<<<dim3(24, 24, 5), dim3(32, 8)>>>(Wg, Ws, pWgh, pWgl, pWsh, pWsl);
    init_x_kernel<<<NUM_L * CC / 256, 256>>>(l_feat, r_feat);

    // GraphGenerator: LR projection, hi-only sim (4-stage), top-16 + rescore
    gemm_mma<3, 2><<<dim3(CC / 128, NTOT / 128), 256, GEMM_SMEM>>>(
        pXh[0], pXl[0], pWgh, pWgl, nullptr, pLRh, pLRl, nullptr, nullptr,
        nullptr, nullptr, nullptr, 0, NTOT, CC, CC, 1);
    gemm_mma<1, 4><<<dim3(NUM_L / 128, NUM_L / 128), 256, GEMM_SMEM>>>(
        pLRh, pLRl, pLRh + (size_t)NUM_L * CC, pLRl + (size_t)NUM_L * CC,
        pSim, nullptr, nullptr, nullptr, nullptr,
        nullptr, nullptr, nullptr, 0, NUM_L, NUM_L, CC, 0);
    topk_rescore_kernel<<<NUM_L, 256>>>();

    // CSR for graph 1
    zero_deg_kernel<<<16, 256>>>();
    count_deg_kernel<<<NUM_L * KSEL / 256, 256>>>();
    scan_off_kernel<<<1, 512>>>();
    init_cursor_kernel<<<16, 256>>>();
    fill_atomic_kernel<<<NUM_L * KSEL / 256, 256>>>();
    sort_convert_kernel<<<16, 256>>>();

    int cur = 0;
    for (int g = 0; g < 2; g++) {
        for (int l = 0; l < NLAYERS; l++) {
            int elu = (l < NLAYERS - 1) ? 1 : 0;
            int final_ = (g == 1 && l == NLAYERS - 1) ? 1 : 0;
            int nxt = cur ^ 1;
            // layer GEMM: reads buf[cur]; fused identity x-out -> buf[nxt] (race-free)
            gemm_mma<3, 2><<<dim3(CC / 128, NTOT / 128), 256, GEMM_SMEM>>>(
                pXh[cur], pXl[cur], pWsh + (size_t)l * CC * CC, pWsl + (size_t)l * CC * CC,
                pZ, nullptr, nullptr,
                a_src + l * HH * DDIM, a_dst + l * HH * DDIM,
                b + l * CC, final_ ? nullptr : pXh[nxt], final_ ? nullptr : pXl[nxt], elu,
                NTOT, CC, CC, 0);
            if (g == 0) agg1_kernel<<<NUM_L, 256>>>(b + l * CC, elu, pXh[nxt], pXl[nxt]);
            else        agg2_kernel<<<NTOT / PPAT, 256>>>(b + l * CC, elu, final_, out,
                                                          pXh[nxt], pXl[nxt]);
            cur = nxt;
        }
    }
}

// round 15
// speedup vs baseline: 1.0429x; 1.0429x over previous
#include <cuda_runtime.h>
#include <cuda_bf16.h>
#include <math.h>
#include <stdint.h>

#define NUM_L   4096
#define NTOT    8192
#define CC      768
#define HH      12
#define DDIM    64
#define KSEL    8
#define PPAT    256
#define NLAYERS 4
#define NEG_SLOPE 0.2f

// ---------------- device scratch ----------------
__device__ float g_sim[NUM_L * NUM_L];          // 64 MB
__device__ int   g_idx[NUM_L * KSEL];
__device__ float g_z [NTOT * CC];
__device__ float g_el[NTOT * HH];
__device__ float g_er[NTOT * HH];
__device__ __nv_bfloat16 g_xh[NTOT * CC], g_xl[NTOT * CC];
__device__ __nv_bfloat16 g_LRh[NTOT * CC], g_LRl[NTOT * CC];
__device__ __nv_bfloat16 g_Wgt_h[CC * CC], g_Wgt_l[CC * CC];
__device__ __nv_bfloat16 g_Wst_h[NLAYERS * CC * CC], g_Wst_l[NLAYERS * CC * CC];
__device__ int   g_deg[NUM_L];
__device__ int   g_off[NUM_L + 1];
__device__ int   g_elist[NUM_L * KSEL];

__device__ __forceinline__ float lrelu(float x) { return x >= 0.f ? x : NEG_SLOPE * x; }

__device__ __forceinline__ uint32_t smem_u32(const void* p) {
    uint32_t a;
    asm("{ .reg .u64 t; cvta.to.shared.u64 t, %1; cvt.u32.u64 %0, t; }" : "=r"(a) : "l"(p));
    return a;
}
__device__ __forceinline__ void split2(float v, __nv_bfloat16& h, __nv_bfloat16& l) {
    h = __float2bfloat16(v);
    l = __float2bfloat16(v - __bfloat162float(h));
}

// ======================= mma.sync bf16 GEMM =======================
// C = A*B^T; A,B bf16 (hi,lo) pairs, K-contiguous. NMMA=3: full split precision.
// NMMA=1: hi*hi only, 2 smem tiles -> NST=4 stages in the same smem budget.
// Optional fused epilogue: el/er per-row head dots vs as_/ad_ (layer GEMMs).
#define SA      40
#define TILE_B  (128 * SA * 2)          // 10240 B per 128x32 tile
#define GEMM_SMEM 81920                 // 2 stages x 4 tiles == 4 stages x 2 tiles

#define CP16(s, g) \
    asm volatile("cp.async.cg.shared.global [%0], [%1], 16;" :: "r"(s), "l"(g))
#define CP_COMMIT() asm volatile("cp.async.commit_group;" ::: "memory")

#define LDSM4(r0, r1, r2, r3, a) \
    asm volatile("ldmatrix.sync.aligned.m8n8.x4.shared.b16 {%0,%1,%2,%3}, [%4];" \
                 : "=r"(r0), "=r"(r1), "=r"(r2), "=r"(r3) : "r"(a))

#define MMA16816(d, a, b) \
    asm volatile("mma.sync.aligned.m16n8k16.row.col.f32.bf16.bf16.f32 " \
                 "{%0,%1,%2,%3},{%4,%5,%6,%7},{%8,%9},{%0,%1,%2,%3};" \
                 : "+f"((d)[0]), "+f"((d)[1]), "+f"((d)[2]), "+f"((d)[3]) \
                 : "r"((a)[0]), "r"((a)[1]), "r"((a)[2]), "r"((a)[3]), \
                   "r"((b)[0]), "r"((b)[1]))

template<int NMMA, int NST>
__global__ void __launch_bounds__(256, 2) gemm_mma(
    const __nv_bfloat16* __restrict__ Ah, const __nv_bfloat16* __restrict__ Al,
    const __nv_bfloat16* __restrict__ Bh, const __nv_bfloat16* __restrict__ Bl,
    float* __restrict__ Cf, __nv_bfloat16* __restrict__ Ch, __nv_bfloat16* __restrict__ Cl,
    const float* __restrict__ as_, const float* __restrict__ ad_,
    int M, int N, int K, int splitout)
{
    extern __shared__ __align__(16) char dsm[];
    __shared__ float s_red[128][2][2];
    const int NTILES = (NMMA == 1) ? 2 : 4;
    const int STB = NTILES * TILE_B;
    const uint32_t sbase = smem_u32(dsm);
    const int tid = threadIdx.x;
    const int wid = tid >> 5, lane = tid & 31;
    const int wm = wid & 1, wn = wid >> 1;
    const int bm = blockIdx.y * 128, bn = blockIdx.x * 128;

    const __nv_bfloat16* srcs[4] = {
        Ah + (size_t)bm * K, Al + (size_t)bm * K,
        Bh + (size_t)bn * K, Bl + (size_t)bn * K };

    const int r0 = tid >> 2, c0 = tid & 3;
    const int r1 = (tid + 256) >> 2, c1 = (tid + 256) & 3;

    const int lj = lane >> 3, lr = lane & 7;
    const uint32_t aoff = (uint32_t)((((lj & 1) * 8 + lr) * SA + (lj >> 1) * 8) * 2);
    const uint32_t boff = (uint32_t)((((lj >> 1) * 8 + lr) * SA + (lj & 1) * 8) * 2);

    float acc[4][4][4];
#pragma unroll
    for (int i = 0; i < 4; i++)
#pragma unroll
        for (int j = 0; j < 4; j++)
#pragma unroll
            for (int k = 0; k < 4; k++) acc[i][j][k] = 0.f;

    const int nc = K >> 5;
    const int NPRO = (NST == 2) ? 2 : (NST - 1);

#pragma unroll
    for (int s = 0; s < NPRO; s++) {
        const uint32_t st = sbase + s * STB;
        const int kb = s * 32;
#pragma unroll
        for (int t = 0; t < 4; t++) {
            if (NMMA == 1 && (t & 1)) continue;
            const int slot = (NMMA == 1) ? (t >> 1) : t;
            const __nv_bfloat16* gp = srcs[t] + kb;
            CP16(st + slot * TILE_B + r0 * (SA * 2) + c0 * 16, gp + (size_t)r0 * K + c0 * 8);
            CP16(st + slot * TILE_B + r1 * (SA * 2) + c1 * 16, gp + (size_t)r1 * K + c1 * 8);
        }
        CP_COMMIT();
    }

    for (int c = 0; c < nc; c++) {
        asm volatile("cp.async.wait_group %0;" :: "n"(NST - 2) : "memory");
        __syncthreads();
        if (NST > 2) {
            // stage c+NST-1 -> buffer (c-1)%NST, freed by the sync above
            if (c + NST - 1 < nc) {
                const uint32_t st2 = sbase + ((c + NST - 1) % NST) * STB;
                const int kb = (c + NST - 1) * 32;
#pragma unroll
                for (int t = 0; t < 4; t++) {
                    if (NMMA == 1 && (t & 1)) continue;
                    const int slot = (NMMA == 1) ? (t >> 1) : t;
                    const __nv_bfloat16* gp = srcs[t] + kb;
                    CP16(st2 + slot * TILE_B + r0 * (SA * 2) + c0 * 16, gp + (size_t)r0 * K + c0 * 8);
                    CP16(st2 + slot * TILE_B + r1 * (SA * 2) + c1 * 16, gp + (size_t)r1 * K + c1 * 8);
                }
            }
            CP_COMMIT();
        }

        const uint32_t st = sbase + (c % NST) * STB;
        const uint32_t sAh = st + (uint32_t)(wm * 64 * SA * 2);
        const uint32_t sAl = st + 1 * TILE_B + (uint32_t)(wm * 64 * SA * 2);
        const uint32_t sBh = st + ((NMMA == 1) ? 1 : 2) * TILE_B + (uint32_t)(wn * 32 * SA * 2);
        const uint32_t sBl = st + 3 * TILE_B + (uint32_t)(wn * 32 * SA * 2);
#pragma unroll
        for (int kk = 0; kk < 2; kk++) {
            const uint32_t kadd = kk * 32;
            uint32_t bh[2][4], bl[2][4];
#pragma unroll
            for (int np = 0; np < 2; np++) {
                const uint32_t noff = (uint32_t)(np * 16 * SA * 2) + kadd;
                LDSM4(bh[np][0], bh[np][1], bh[np][2], bh[np][3], sBh + noff + boff);
                if (NMMA == 3)
                    LDSM4(bl[np][0], bl[np][1], bl[np][2], bl[np][3], sBl + noff + boff);
            }
#pragma unroll
            for (int mt = 0; mt < 4; mt++) {
                uint32_t ah[4], al[4];
                const uint32_t moff = (uint32_t)(mt * 16 * SA * 2) + kadd;
                LDSM4(ah[0], ah[1], ah[2], ah[3], sAh + moff + aoff);
                if (NMMA == 3)
                    LDSM4(al[0], al[1], al[2], al[3], sAl + moff + aoff);
#pragma unroll
                for (int nt = 0; nt < 4; nt++) {
                    const uint32_t* bhf = &bh[nt >> 1][(nt & 1) * 2];
                    MMA16816(acc[mt][nt], ah, bhf);
                    if (NMMA == 3) {
                        const uint32_t* blf = &bl[nt >> 1][(nt & 1) * 2];
                        MMA16816(acc[mt][nt], ah, blf);
                        MMA16816(acc[mt][nt], al, bhf);
                    }
                }
            }
        }
        if (NST == 2) {
            __syncthreads();
            if (c + 2 < nc) {
                const int kb = (c + 2) * 32;
#pragma unroll
                for (int t = 0; t < 4; t++) {
                    if (NMMA == 1 && (t & 1)) continue;
                    const int slot = (NMMA == 1) ? (t >> 1) : t;
                    const __nv_bfloat16* gp = srcs[t] + kb;
                    CP16(st + slot * TILE_B + r0 * (SA * 2) + c0 * 16, gp + (size_t)r0 * K + c0 * 8);
                    CP16(st + slot * TILE_B + r1 * (SA * 2) + c1 * 16, gp + (size_t)r1 * K + c1 * 8);
                }
            }
            CP_COMMIT();
        }
    }

    const int er = lane >> 2, ec = (lane & 3) * 2;

    // ---- C store ----
#pragma unroll
    for (int mt = 0; mt < 4; mt++) {
        const int row = bm + wm * 64 + mt * 16 + er;
#pragma unroll
        for (int nt = 0; nt < 4; nt++) {
            const int col = bn + wn * 32 + nt * 8 + ec;
            if (!splitout) {
                float2* p0 = (float2*)(Cf + (size_t)row * N + col);
                float2* p1 = (float2*)(Cf + (size_t)(row + 8) * N + col);
                *p0 = make_float2(acc[mt][nt][0], acc[mt][nt][1]);
                *p1 = make_float2(acc[mt][nt][2], acc[mt][nt][3]);
            } else {
#pragma unroll
                for (int half = 0; half < 2; half++) {
                    const size_t o = (size_t)(row + half * 8) * N + col;
                    __nv_bfloat16 h0, l0, h1, l1;
                    split2(acc[mt][nt][half * 2 + 0], h0, l0);
                    split2(acc[mt][nt][half * 2 + 1], h1, l1);
                    __nv_bfloat162 hv; hv.x = h0; hv.y = h1;
                    __nv_bfloat162 lv2; lv2.x = l0; lv2.y = l1;
                    *(__nv_bfloat162*)(Ch + o) = hv;
                    *(__nv_bfloat162*)(Cl + o) = lv2;
                }
            }
        }
    }

    // ---- fused el/er epilogue (layer GEMMs; N == 768, heads of 64 cols) ----
    if (as_ != nullptr) {
        const int h    = (bn + wn * 32) >> 6;
        const int hl   = wn >> 1;
        const int cih0 = (wn & 1) * 32;
        float elv[4][2], erv[4][2];
#pragma unroll
        for (int mt = 0; mt < 4; mt++) { elv[mt][0] = elv[mt][1] = erv[mt][0] = erv[mt][1] = 0.f; }
#pragma unroll
        for (int nt = 0; nt < 4; nt++) {
            const int cih = cih0 + nt * 8 + ec;
            const float a0 = as_[h * DDIM + cih], a1 = as_[h * DDIM + cih + 1];
            const float d0 = ad_[h * DDIM + cih], d1 = ad_[h * DDIM + cih + 1];
#pragma unroll
            for (int mt = 0; mt < 4; mt++) {
                elv[mt][0] += acc[mt][nt][0] * a0 + acc[mt][nt][1] * a1;
                elv[mt][1] += acc[mt][nt][2] * a0 + acc[mt][nt][3] * a1;
                erv[mt][0] += acc[mt][nt][0] * d0 + acc[mt][nt][1] * d1;
                erv[mt][1] += acc[mt][nt][2] * d0 + acc[mt][nt][3] * d1;
            }
        }
#pragma unroll
        for (int mt = 0; mt < 4; mt++)
#pragma unroll
            for (int hf = 0; hf < 2; hf++) {
#pragma unroll
                for (int o = 1; o <= 2; o <<= 1) {
                    elv[mt][hf] += __shfl_xor_sync(0xffffffffu, elv[mt][hf], o);
                    erv[mt][hf] += __shfl_xor_sync(0xffffffffu, erv[mt][hf], o);
                }
            }
        __syncthreads();
        if ((wn & 1) == 0 && (lane & 3) == 0) {
#pragma unroll
            for (int mt = 0; mt < 4; mt++)
#pragma unroll
                for (int hf = 0; hf < 2; hf++) {
                    const int r = wm * 64 + mt * 16 + er + hf * 8;
                    s_red[r][hl][0] = elv[mt][hf];
                    s_red[r][hl][1] = erv[mt][hf];
                }
        }
        __syncthreads();
        if ((wn & 1) == 1 && (lane & 3) == 0) {
#pragma unroll
            for (int mt = 0; mt < 4; mt++)
#pragma unroll
                for (int hf = 0; hf < 2; hf++) {
                    const int r = wm * 64 + mt * 16 + er + hf * 8;
                    g_el[(size_t)(bm + r) * HH + h] = s_red[r][hl][0] + elv[mt][hf];
                    g_er[(size_t)(bm + r) * HH + h] = s_red[r][hl][1] + erv[mt][hf];
                }
        }
    }
}

// ---------------- batched 768x768 transpose + split ----------------
__global__ void transpose_split_all(const float* __restrict__ Wg,
                                    const float* __restrict__ Ws,
                                    __nv_bfloat16* __restrict__ WgH, __nv_bfloat16* __restrict__ WgL,
                                    __nv_bfloat16* __restrict__ WsH, __nv_bfloat16* __restrict__ WsL) {
    __shared__ float t[32][33];
    int zi = blockIdx.z;
    const float* src = (zi == 0) ? Wg : Ws + (size_t)(zi - 1) * CC * CC;
    __nv_bfloat16* dh = (zi == 0) ? WgH : WsH + (size_t)(zi - 1) * CC * CC;
    __nv_bfloat16* dl = (zi == 0) ? WgL : WsL + (size_t)(zi - 1) * CC * CC;
    int bx = blockIdx.x * 32, by = blockIdx.y * 32;
    int x = bx + threadIdx.x;
#pragma unroll
    for (int j = 0; j < 32; j += 8)
        t[threadIdx.y + j][threadIdx.x] = src[(size_t)(by + threadIdx.y + j) * CC + x];
    __syncthreads();
    int x2 = by + threadIdx.x;
#pragma unroll
    for (int j = 0; j < 32; j += 8) {
        float v = t[threadIdx.x][threadIdx.y + j];
        size_t o = (size_t)(bx + threadIdx.y + j) * CC + x2;
        __nv_bfloat16 h, l; split2(v, h, l);
        dh[o] = h; dl[o] = l;
    }
}

// ---------------- top-16 candidates + fp32 rescore + exact top-8 ----------------
__global__ __launch_bounds__(256) void topk_rescore_kernel() {
    __shared__ float sv[NUM_L];
    __shared__ float rv[256];
    __shared__ int   ri[256];
    __shared__ int   cand[16];
    __shared__ float cs[16];
    __shared__ float lrow[CC];
    int r = blockIdx.x, tid = threadIdx.x;
    const float* row = g_sim + (size_t)r * NUM_L;
    for (int c = tid; c < NUM_L; c += 256) sv[c] = row[c];
    __syncthreads();
    for (int t = 0; t < 16; t++) {
        float bv = -INFINITY; int bi = NUM_L;
        for (int c = tid; c < NUM_L; c += 256) {
            float v = sv[c];
            if (v > bv || (v == bv && c < bi)) { bv = v; bi = c; }
        }
        rv[tid] = bv; ri[tid] = bi;
        __syncthreads();
        for (int s = 128; s > 0; s >>= 1) {
            if (tid < s) {
                float v = rv[tid + s]; int i2 = ri[tid + s];
                if (v > rv[tid] || (v == rv[tid] && i2 < ri[tid])) { rv[tid] = v; ri[tid] = i2; }
            }
            __syncthreads();
        }
        if (tid == 0) { cand[t] = ri[0]; sv[ri[0]] = -INFINITY; }
        __syncthreads();
    }
    for (int d = tid; d < CC; d += 256)
        lrow[d] = __bfloat162float(g_LRh[(size_t)r * CC + d])
                + __bfloat162float(g_LRl[(size_t)r * CC + d]);
    __syncthreads();
    int wid = tid >> 5, lane = tid & 31;
    for (int c = wid; c < 16; c += 8) {
        size_t rr = (size_t)(cand[c] + NUM_L) * CC;
        float s = 0.f;
        for (int d = lane; d < CC; d += 32)
            s += lrow[d] * (__bfloat162float(g_LRh[rr + d]) + __bfloat162float(g_LRl[rr + d]));
#pragma unroll
        for (int o = 16; o; o >>= 1) s += __shfl_xor_sync(0xffffffffu, s, o);
        if (lane == 0) cs[c] = s;
    }
    __syncthreads();
    if (tid == 0) {
        unsigned used = 0;
        for (int t = 0; t < KSEL; t++) {
            float bv = -INFINITY; int bslot = 0, bidx = NUM_L;
            for (int c = 0; c < 16; c++) {
                if (used & (1u << c)) continue;
                if (cs[c] > bv || (cs[c] == bv && cand[c] < bidx)) {
                    bv = cs[c]; bidx = cand[c]; bslot = c;
                }
            }
            used |= 1u << bslot;
            g_idx[r * KSEL + t] = bidx;
        }
    }
}

// ---------------- CSR build ----------------
__global__ void zero_deg_kernel() {
    int i = blockIdx.x * 256 + threadIdx.x;
    if (i < NUM_L) g_deg[i] = 0;
}
__global__ void count_deg_kernel() {
    int e = blockIdx.x * 256 + threadIdx.x;
    if (e < NUM_L * KSEL) atomicAdd(&g_deg[g_idx[e]], 1);
}
__global__ __launch_bounds__(512) void scan_off_kernel() {
    __shared__ int ss[512];
    int tid = threadIdx.x;
    int base = tid * 8;
    int loc[8]; int s = 0;
#pragma unroll
    for (int i = 0; i < 8; i++) { loc[i] = s; s += g_deg[base + i]; }
    ss[tid] = s; __syncthreads();
    for (int d = 1; d < 512; d <<= 1) {
        int v = (tid >= d) ? ss[tid - d] : 0;
        __syncthreads();
        ss[tid] += v;
        __syncthreads();
    }
    int excl = ss[tid] - s;
#pragma unroll
    for (int i = 0; i < 8; i++) g_off[base + i] = excl + loc[i];
    if (tid == 511) g_off[NUM_L] = ss[511];
}
__global__ void init_cursor_kernel() {
    int i = blockIdx.x * 256 + threadIdx.x;
    if (i < NUM_L) g_deg[i] = g_off[i];
}
__global__ void fill_atomic_kernel() {
    int e = blockIdx.x * 256 + threadIdx.x;
    if (e < NUM_L * KSEL) {
        int pos = atomicAdd(&g_deg[g_idx[e]], 1);
        g_elist[pos] = e;
    }
}
__global__ void sort_convert_kernel() {
    int j = blockIdx.x * 256 + threadIdx.x;
    if (j >= NUM_L) return;
    int e0 = g_off[j], e1 = g_off[j + 1];
    for (int i = e0 + 1; i < e1; i++) {
        int key = g_elist[i];
        int k = i - 1;
        while (k >= e0 && g_elist[k] > key) { g_elist[k + 1] = g_elist[k]; k--; }
        g_elist[k + 1] = key;
    }
    for (int i = e0; i < e1; i++) g_elist[i] >>= 3;
}

// ---------------- x init ----------------
__global__ void init_x_kernel(const float* __restrict__ l, const float* __restrict__ r) {
    int i = blockIdx.x * 256 + threadIdx.x;
    if (i < NUM_L * CC) {
        split2(l[i], g_xh[i], g_xl[i]);
        split2(r[i], g_xh[NUM_L * CC + i], g_xl[NUM_L * CC + i]);
    }
}

// ---------------- fused bias + act + split ----------------
__device__ __forceinline__ void store_x(int n, int d, float v, int elu) {
    if (elu) v = v > 0.f ? v : expm1f(v);
    size_t o = (size_t)n * CC + d;
    split2(v, g_xh[o], g_xl[o]);
}

// ---------------- 12-channel block reductions ----------------
__device__ __forceinline__ void block_max12(float* lv, float* red, float* outp, int tid) {
#pragma unroll
    for (int h = 0; h < HH; h++)
#pragma unroll
        for (int o = 16; o; o >>= 1)
            lv[h] = fmaxf(lv[h], __shfl_xor_sync(0xffffffffu, lv[h], o));
    if ((tid & 31) == 0)
#pragma unroll
        for (int h = 0; h < HH; h++) red[(tid >> 5) * HH + h] = lv[h];
    __syncthreads();
    if (tid < HH) {
        float v = red[tid];
#pragma unroll
        for (int w = 1; w < 8; w++) v = fmaxf(v, red[w * HH + tid]);
        outp[tid] = v;
    }
    __syncthreads();
}
__device__ __forceinline__ void block_sum12(float* lv, float* red, float* outp, int tid) {
#pragma unroll
    for (int h = 0; h < HH; h++)
#pragma unroll
        for (int o = 16; o; o >>= 1)
            lv[h] += __shfl_xor_sync(0xffffffffu, lv[h], o);
    if ((tid & 31) == 0)
#pragma unroll
        for (int h = 0; h < HH; h++) red[(tid >> 5) * HH + h] = lv[h];
    __syncthreads();
    if (tid < HH) {
        float v = red[tid];
#pragma unroll
        for (int w = 1; w < 8; w++) v += red[w * HH + tid];
        outp[tid] = v;
    }
    __syncthreads();
}

// ---------------- GAT aggregation + act, graph 1 ----------------
__global__ __launch_bounds__(256) void agg1_kernel(const float* __restrict__ bias, int elu) {
    int n = blockIdx.x, tid = threadIdx.x;
    if (n < NUM_L) {   // left nodes: self loop only -> out = act(z + b)
        for (int d = tid; d < CC; d += 256)
            store_x(n, d, g_z[(size_t)n * CC + d] + bias[d], elu);
        return;
    }
    __shared__ float s_er[HH], s_m[HH], s_sum[HH], s_inv[HH];
    __shared__ float red[8 * HH];
    int j = n - NUM_L;
    int e0 = g_off[j], e1 = g_off[j + 1];
    int deg = e1 - e0;
    if (tid < HH) s_er[tid] = g_er[n * HH + tid];
    __syncthreads();

    float lv[HH];
#pragma unroll
    for (int h = 0; h < HH; h++) lv[h] = -INFINITY;
    for (int t = tid; t < deg + 1; t += 256) {
        int src = (t < deg) ? g_elist[e0 + t] : n;
        const float* elp = g_el + src * HH;
#pragma unroll
        for (int h = 0; h < HH; h++) lv[h] = fmaxf(lv[h], lrelu(elp[h] + s_er[h]));
    }
    block_max12(lv, red, s_m, tid);

#pragma unroll
    for (int h = 0; h < HH; h++) lv[h] = 0.f;
    for (int t = tid; t < deg + 1; t += 256) {
        int src = (t < deg) ? g_elist[e0 + t] : n;
        const float* elp = g_el + src * HH;
#pragma unroll
        for (int h = 0; h < HH; h++) lv[h] += expf(lrelu(elp[h] + s_er[h]) - s_m[h]);
    }
    block_sum12(lv, red, s_sum, tid);
    if (tid < HH) s_inv[tid] = 1.f / s_sum[tid];
    __syncthreads();

    for (int d = tid; d < CC; d += 256) {
        int h = d >> 6;
        float m = s_m[h], inv = s_inv[h], erh = s_er[h];
        float acc = expf(lrelu(g_el[n * HH + h] + erh) - m) * inv * g_z[(size_t)n * CC + d];
        for (int e = e0; e < e1; e++) {
            int src = g_elist[e];
            acc += expf(lrelu(g_el[src * HH + h] + erh) - m) * inv * g_z[(size_t)src * CC + d];
        }
        store_x(n, d, acc + bias[d], elu);
    }
}

// ---------------- GAT aggregation + act, graph 2 ----------------
__global__ __launch_bounds__(256) void agg2_kernel(const float* __restrict__ bias,
                                                   int elu, int final_, float* outp) {
    int n = blockIdx.x, tid = threadIdx.x;
    if (n & (PPAT - 1)) {
        if (final_) return;   // last layer: non-image outputs never read
        for (int d = tid; d < CC; d += 256)
            store_x(n, d, g_z[(size_t)n * CC + d] + bias[d], elu);
        return;
    }
    __shared__ float s_er[HH], s_m[HH], s_sum[HH], s_inv[HH];
    __shared__ float s_w[PPAT * HH];
    __shared__ float red[8 * HH];
    if (tid < HH) s_er[tid] = g_er[n * HH + tid];
    __syncthreads();

    int src = n + tid;
    float ev[HH];
    const float* elp = g_el + src * HH;
#pragma unroll
    for (int h = 0; h < HH; h++) ev[h] = lrelu(elp[h] + s_er[h]);

    float lv[HH];
#pragma unroll
    for (int h = 0; h < HH; h++) lv[h] = ev[h];
    block_max12(lv, red, s_m, tid);

    float mult = (tid == 0) ? 2.f : 1.f;   // duplicated self edge
    float ex[HH];
#pragma unroll
    for (int h = 0; h < HH; h++) { ex[h] = expf(ev[h] - s_m[h]) * mult; lv[h] = ex[h]; }
    block_sum12(lv, red, s_sum, tid);
    if (tid < HH) s_inv[tid] = 1.f / s_sum[tid];
    __syncthreads();
#pragma unroll
    for (int h = 0; h < HH; h++) s_w[tid * HH + h] = ex[h] * s_inv[h];
    __syncthreads();

    for (int d = tid; d < CC; d += 256) {
        int h = d >> 6;
        float acc = 0.f;
        for (int i = 0; i < PPAT; i++)
            acc += s_w[i * HH + h] * g_z[(size_t)(n + i) * CC + d];
        float v = acc + bias[d];
        if (final_) {
            if (elu) v = v > 0.f ? v : expm1f(v);
            outp[(size_t)(n / PPAT) * CC + d] = v;
        } else {
            store_x(n, d, v, elu);
        }
    }
}

// ---------------- launch ----------------
extern "C" void kernel_launch(void* const* d_in, const int* in_sizes, int n_in,
                              void* d_out, int out_size) {
    (void)in_sizes; (void)n_in; (void)out_size;
    const float* l_feat = (const float*)d_in[0];
    const float* r_feat = (const float*)d_in[1];
    const float* Wg     = (const float*)d_in[2];
    const float* Ws     = (const float*)d_in[3];
    const float* a_src  = (const float*)d_in[4];
    const float* a_dst  = (const float*)d_in[5];
    const float* b      = (const float*)d_in[6];
    float* out = (float*)d_out;

    cudaFuncSetAttribute(gemm_mma<3, 2>, cudaFuncAttributeMaxDynamicSharedMemorySize, GEMM_SMEM);
    cudaFuncSetAttribute(gemm_mma<1, 4>, cudaFuncAttributeMaxDynamicSharedMemorySize, GEMM_SMEM);

    __nv_bfloat16 *pWgh, *pWgl, *pWsh, *pWsl, *pxh, *pxl, *pLRh, *pLRl;
    float *pSim, *pZ;
    cudaGetSymbolAddress((void**)&pWgh, g_Wgt_h);
    cudaGetSymbolAddress((void**)&pWgl, g_Wgt_l);
    cudaGetSymbolAddress((void**)&pWsh, g_Wst_h);
    cudaGetSymbolAddress((void**)&pWsl, g_Wst_l);
    cudaGetSymbolAddress((void**)&pxh,  g_xh);
    cudaGetSymbolAddress((void**)&pxl,  g_xl);
    cudaGetSymbolAddress((void**)&pLRh, g_LRh);
    cudaGetSymbolAddress((void**)&pLRl, g_LRl);
    cudaGetSymbolAddress((void**)&pSim, g_sim);
    cudaGetSymbolAddress((void**)&pZ,   g_z);

    transpose_split_all<<<dim3(24, 24, 5), dim3(32, 8)>>>(Wg, Ws, pWgh, pWgl, pWsh, pWsl);
    init_x_kernel<<<NUM_L * CC / 256, 256>>>(l_feat, r_feat);

    // GraphGenerator: LR projection, hi-only sim (4-stage), top-16 + rescore
    gemm_mma<3, 2><<<dim3(CC / 128, NTOT / 128), 256, GEMM_SMEM>>>(
        pxh, pxl, pWgh, pWgl, nullptr, pLRh, pLRl, nullptr, nullptr, NTOT, CC, CC, 1);
    gemm_mma<1, 4><<<dim3(NUM_L / 128, NUM_L / 128), 256, GEMM_SMEM>>>(
        pLRh, pLRl, pLRh + (size_t)NUM_L * CC, pLRl + (size_t)NUM_L * CC,
        pSim, nullptr, nullptr, nullptr, nullptr, NUM_L, NUM_L, CC, 0);
    topk_rescore_kernel<<<NUM_L, 256>>>();

    // CSR for graph 1
    zero_deg_kernel<<<16, 256>>>();
    count_deg_kernel<<<NUM_L * KSEL / 256, 256>>>();
    scan_off_kernel<<<1, 512>>>();
    init_cursor_kernel<<<16, 256>>>();
    fill_atomic_kernel<<<NUM_L * KSEL / 256, 256>>>();
    sort_convert_kernel<<<16, 256>>>();

    for (int g = 0; g < 2; g++) {
        for (int l = 0; l < NLAYERS; l++) {
            gemm_mma<3, 2><<<dim3(CC / 128, NTOT / 128), 256, GEMM_SMEM>>>(
                pxh, pxl, pWsh + (size_t)l * CC * CC, pWsl + (size_t)l * CC * CC,
                pZ, nullptr, nullptr,
                a_src + l * HH * DDIM, a_dst + l * HH * DDIM, NTOT, CC, CC, 0);
            int elu = (l < NLAYERS - 1) ? 1 : 0;
            if (g == 0) agg1_kernel<<<NTOT, 256>>>(b + l * CC, elu);
            else        agg2_kernel<<<NTOT, 256>>>(b + l * CC, elu,
                                                   (l == NLAYERS - 1) ? 1 : 0, out);
        }
    }
}

// round 16
// speedup vs baseline: 1.0809x; 1.0364x over previous
#include <cuda_runtime.h>
#include <cuda_bf16.h>
#include <math.h>
#include <stdint.h>

#define NUM_L   4096
#define NTOT    8192
#define CC      768
#define HH      12
#define DDIM    64
#define KSEL    8
#define PPAT    256
#define NLAYERS 4
#define NEG_SLOPE 0.2f

// ---------------- device scratch ----------------
__device__ float g_sim[NUM_L * NUM_L];          // 64 MB
__device__ int   g_idx[NUM_L * KSEL];
__device__ float g_z [NTOT * CC];
__device__ float g_el[NTOT * HH];
__device__ float g_er[NTOT * HH];
__device__ __nv_bfloat16 g_xh[NTOT * CC], g_xl[NTOT * CC];
__device__ __nv_bfloat16 g_LRh[NTOT * CC], g_LRl[NTOT * CC];
__device__ __nv_bfloat16 g_Wgt_h[CC * CC], g_Wgt_l[CC * CC];
__device__ __nv_bfloat16 g_Wst_h[NLAYERS * CC * CC], g_Wst_l[NLAYERS * CC * CC];
__device__ int   g_deg[NUM_L];
__device__ int   g_off[NUM_L + 1];
__device__ int   g_elist[NUM_L * KSEL];

__device__ __forceinline__ float lrelu(float x) { return x >= 0.f ? x : NEG_SLOPE * x; }

__device__ __forceinline__ uint32_t smem_u32(const void* p) {
    uint32_t a;
    asm("{ .reg .u64 t; cvta.to.shared.u64 t, %1; cvt.u32.u64 %0, t; }" : "=r"(a) : "l"(p));
    return a;
}
__device__ __forceinline__ void split2(float v, __nv_bfloat16& h, __nv_bfloat16& l) {
    h = __float2bfloat16(v);
    l = __float2bfloat16(v - __bfloat162float(h));
}

// ======================= mma.sync bf16 GEMM =======================
// C = A*B^T; A,B bf16 (hi,lo) pairs, K-contiguous. NMMA=3: full split precision.
// NMMA=1: hi*hi only, 2 smem tiles -> NST=4 stages in the same smem budget.
// Optional fused epilogue: el/er per-row head dots vs as_/ad_ (layer GEMMs).
#define SA      40
#define TILE_B  (128 * SA * 2)          // 10240 B per 128x32 tile
#define GEMM_SMEM 81920                 // 2 stages x 4 tiles == 4 stages x 2 tiles

#define CP16(s, g) \
    asm volatile("cp.async.cg.shared.global [%0], [%1], 16;" :: "r"(s), "l"(g))
#define CP_COMMIT() asm volatile("cp.async.commit_group;" ::: "memory")

#define LDSM4(r0, r1, r2, r3, a) \
    asm volatile("ldmatrix.sync.aligned.m8n8.x4.shared.b16 {%0,%1,%2,%3}, [%4];" \
                 : "=r"(r0), "=r"(r1), "=r"(r2), "=r"(r3) : "r"(a))

#define MMA16816(d, a, b) \
    asm volatile("mma.sync.aligned.m16n8k16.row.col.f32.bf16.bf16.f32 " \
                 "{%0,%1,%2,%3},{%4,%5,%6,%7},{%8,%9},{%0,%1,%2,%3};" \
                 : "+f"((d)[0]), "+f"((d)[1]), "+f"((d)[2]), "+f"((d)[3]) \
                 : "r"((a)[0]), "r"((a)[1]), "r"((a)[2]), "r"((a)[3]), \
                   "r"((b)[0]), "r"((b)[1]))

template<int NMMA, int NST>
__global__ void __launch_bounds__(256, 2) gemm_mma(
    const __nv_bfloat16* __restrict__ Ah, const __nv_bfloat16* __restrict__ Al,
    const __nv_bfloat16* __restrict__ Bh, const __nv_bfloat16* __restrict__ Bl,
    float* __restrict__ Cf, __nv_bfloat16* __restrict__ Ch, __nv_bfloat16* __restrict__ Cl,
    const float* __restrict__ as_, const float* __restrict__ ad_,
    int M, int N, int K, int splitout)
{
    extern __shared__ __align__(16) char dsm[];
    __shared__ float s_red[128][2][2];
    const int NTILES = (NMMA == 1) ? 2 : 4;
    const int STB = NTILES * TILE_B;
    // Wait depth: NST=2 issues at loop BOTTOM (pending at wait: {c, c+1}) -> 1.
    // NST=4 issues at loop TOP after the wait (pending: {c, c+1, c+2}) -> NST-2.
    constexpr int WG = (NST == 2) ? 1 : (NST - 2);
    const uint32_t sbase = smem_u32(dsm);
    const int tid = threadIdx.x;
    const int wid = tid >> 5, lane = tid & 31;
    const int wm = wid & 1, wn = wid >> 1;
    const int bm = blockIdx.y * 128, bn = blockIdx.x * 128;

    const __nv_bfloat16* srcs[4] = {
        Ah + (size_t)bm * K, Al + (size_t)bm * K,
        Bh + (size_t)bn * K, Bl + (size_t)bn * K };

    const int r0 = tid >> 2, c0 = tid & 3;
    const int r1 = (tid + 256) >> 2, c1 = (tid + 256) & 3;

    const int lj = lane >> 3, lr = lane & 7;
    const uint32_t aoff = (uint32_t)((((lj & 1) * 8 + lr) * SA + (lj >> 1) * 8) * 2);
    const uint32_t boff = (uint32_t)((((lj >> 1) * 8 + lr) * SA + (lj & 1) * 8) * 2);

    float acc[4][4][4];
#pragma unroll
    for (int i = 0; i < 4; i++)
#pragma unroll
        for (int j = 0; j < 4; j++)
#pragma unroll
            for (int k = 0; k < 4; k++) acc[i][j][k] = 0.f;

    const int nc = K >> 5;
    const int NPRO = (NST == 2) ? 2 : (NST - 1);

#pragma unroll
    for (int s = 0; s < NPRO; s++) {
        const uint32_t st = sbase + s * STB;
        const int kb = s * 32;
#pragma unroll
        for (int t = 0; t < 4; t++) {
            if (NMMA == 1 && (t & 1)) continue;
            const int slot = (NMMA == 1) ? (t >> 1) : t;
            const __nv_bfloat16* gp = srcs[t] + kb;
            CP16(st + slot * TILE_B + r0 * (SA * 2) + c0 * 16, gp + (size_t)r0 * K + c0 * 8);
            CP16(st + slot * TILE_B + r1 * (SA * 2) + c1 * 16, gp + (size_t)r1 * K + c1 * 8);
        }
        CP_COMMIT();
    }

    for (int c = 0; c < nc; c++) {
        asm volatile("cp.async.wait_group %0;" :: "n"(WG) : "memory");
        __syncthreads();
        if (NST > 2) {
            // stage c+NST-1 -> buffer (c-1)%NST, freed by the sync above
            if (c + NST - 1 < nc) {
                const uint32_t st2 = sbase + ((c + NST - 1) % NST) * STB;
                const int kb = (c + NST - 1) * 32;
#pragma unroll
                for (int t = 0; t < 4; t++) {
                    if (NMMA == 1 && (t & 1)) continue;
                    const int slot = (NMMA == 1) ? (t >> 1) : t;
                    const __nv_bfloat16* gp = srcs[t] + kb;
                    CP16(st2 + slot * TILE_B + r0 * (SA * 2) + c0 * 16, gp + (size_t)r0 * K + c0 * 8);
                    CP16(st2 + slot * TILE_B + r1 * (SA * 2) + c1 * 16, gp + (size_t)r1 * K + c1 * 8);
                }
            }
            CP_COMMIT();
        }

        const uint32_t st = sbase + (c % NST) * STB;
        const uint32_t sAh = st + (uint32_t)(wm * 64 * SA * 2);
        const uint32_t sAl = st + 1 * TILE_B + (uint32_t)(wm * 64 * SA * 2);
        const uint32_t sBh = st + ((NMMA == 1) ? 1 : 2) * TILE_B + (uint32_t)(wn * 32 * SA * 2);
        const uint32_t sBl = st + 3 * TILE_B + (uint32_t)(wn * 32 * SA * 2);
#pragma unroll
        for (int kk = 0; kk < 2; kk++) {
            const uint32_t kadd = kk * 32;
            uint32_t bh[2][4], bl[2][4];
#pragma unroll
            for (int np = 0; np < 2; np++) {
                const uint32_t noff = (uint32_t)(np * 16 * SA * 2) + kadd;
                LDSM4(bh[np][0], bh[np][1], bh[np][2], bh[np][3], sBh + noff + boff);
                if (NMMA == 3)
                    LDSM4(bl[np][0], bl[np][1], bl[np][2], bl[np][3], sBl + noff + boff);
            }
#pragma unroll
            for (int mt = 0; mt < 4; mt++) {
                uint32_t ah[4], al[4];
                const uint32_t moff = (uint32_t)(mt * 16 * SA * 2) + kadd;
                LDSM4(ah[0], ah[1], ah[2], ah[3], sAh + moff + aoff);
                if (NMMA == 3)
                    LDSM4(al[0], al[1], al[2], al[3], sAl + moff + aoff);
#pragma unroll
                for (int nt = 0; nt < 4; nt++) {
                    const uint32_t* bhf = &bh[nt >> 1][(nt & 1) * 2];
                    MMA16816(acc[mt][nt], ah, bhf);
                    if (NMMA == 3) {
                        const uint32_t* blf = &bl[nt >> 1][(nt & 1) * 2];
                        MMA16816(acc[mt][nt], ah, blf);
                        MMA16816(acc[mt][nt], al, bhf);
                    }
                }
            }
        }
        if (NST == 2) {
            __syncthreads();
            if (c + 2 < nc) {
                const int kb = (c + 2) * 32;
#pragma unroll
                for (int t = 0; t < 4; t++) {
                    if (NMMA == 1 && (t & 1)) continue;
                    const int slot = (NMMA == 1) ? (t >> 1) : t;
                    const __nv_bfloat16* gp = srcs[t] + kb;
                    CP16(st + slot * TILE_B + r0 * (SA * 2) + c0 * 16, gp + (size_t)r0 * K + c0 * 8);
                    CP16(st + slot * TILE_B + r1 * (SA * 2) + c1 * 16, gp + (size_t)r1 * K + c1 * 8);
                }
            }
            CP_COMMIT();
        }
    }

    const int er = lane >> 2, ec = (lane & 3) * 2;

    // ---- C store ----
#pragma unroll
    for (int mt = 0; mt < 4; mt++) {
        const int row = bm + wm * 64 + mt * 16 + er;
#pragma unroll
        for (int nt = 0; nt < 4; nt++) {
            const int col = bn + wn * 32 + nt * 8 + ec;
            if (!splitout) {
                float2* p0 = (float2*)(Cf + (size_t)row * N + col);
                float2* p1 = (float2*)(Cf + (size_t)(row + 8) * N + col);
                *p0 = make_float2(acc[mt][nt][0], acc[mt][nt][1]);
                *p1 = make_float2(acc[mt][nt][2], acc[mt][nt][3]);
            } else {
#pragma unroll
                for (int half = 0; half < 2; half++) {
                    const size_t o = (size_t)(row + half * 8) * N + col;
                    __nv_bfloat16 h0, l0, h1, l1;
                    split2(acc[mt][nt][half * 2 + 0], h0, l0);
                    split2(acc[mt][nt][half * 2 + 1], h1, l1);
                    __nv_bfloat162 hv; hv.x = h0; hv.y = h1;
                    __nv_bfloat162 lv2; lv2.x = l0; lv2.y = l1;
                    *(__nv_bfloat162*)(Ch + o) = hv;
                    *(__nv_bfloat162*)(Cl + o) = lv2;
                }
            }
        }
    }

    // ---- fused el/er epilogue (layer GEMMs; N == 768, heads of 64 cols) ----
    if (as_ != nullptr) {
        const int h    = (bn + wn * 32) >> 6;
        const int hl   = wn >> 1;
        const int cih0 = (wn & 1) * 32;
        float elv[4][2], erv[4][2];
#pragma unroll
        for (int mt = 0; mt < 4; mt++) { elv[mt][0] = elv[mt][1] = erv[mt][0] = erv[mt][1] = 0.f; }
#pragma unroll
        for (int nt = 0; nt < 4; nt++) {
            const int cih = cih0 + nt * 8 + ec;
            const float a0 = as_[h * DDIM + cih], a1 = as_[h * DDIM + cih + 1];
            const float d0 = ad_[h * DDIM + cih], d1 = ad_[h * DDIM + cih + 1];
#pragma unroll
            for (int mt = 0; mt < 4; mt++) {
                elv[mt][0] += acc[mt][nt][0] * a0 + acc[mt][nt][1] * a1;
                elv[mt][1] += acc[mt][nt][2] * a0 + acc[mt][nt][3] * a1;
                erv[mt][0] += acc[mt][nt][0] * d0 + acc[mt][nt][1] * d1;
                erv[mt][1] += acc[mt][nt][2] * d0 + acc[mt][nt][3] * d1;
            }
        }
#pragma unroll
        for (int mt = 0; mt < 4; mt++)
#pragma unroll
            for (int hf = 0; hf < 2; hf++) {
#pragma unroll
                for (int o = 1; o <= 2; o <<= 1) {
                    elv[mt][hf] += __shfl_xor_sync(0xffffffffu, elv[mt][hf], o);
                    erv[mt][hf] += __shfl_xor_sync(0xffffffffu, erv[mt][hf], o);
                }
            }
        __syncthreads();
        if ((wn & 1) == 0 && (lane & 3) == 0) {
#pragma unroll
            for (int mt = 0; mt < 4; mt++)
#pragma unroll
                for (int hf = 0; hf < 2; hf++) {
                    const int r = wm * 64 + mt * 16 + er + hf * 8;
                    s_red[r][hl][0] = elv[mt][hf];
                    s_red[r][hl][1] = erv[mt][hf];
                }
        }
        __syncthreads();
        if ((wn & 1) == 1 && (lane & 3) == 0) {
#pragma unroll
            for (int mt = 0; mt < 4; mt++)
#pragma unroll
                for (int hf = 0; hf < 2; hf++) {
                    const int r = wm * 64 + mt * 16 + er + hf * 8;
                    g_el[(size_t)(bm + r) * HH + h] = s_red[r][hl][0] + elv[mt][hf];
                    g_er[(size_t)(bm + r) * HH + h] = s_red[r][hl][1] + erv[mt][hf];
                }
        }
    }
}

// ---------------- batched 768x768 transpose + split ----------------
__global__ void transpose_split_all(const float* __restrict__ Wg,
                                    const float* __restrict__ Ws,
                                    __nv_bfloat16* __restrict__ WgH, __nv_bfloat16* __restrict__ WgL,
                                    __nv_bfloat16* __restrict__ WsH, __nv_bfloat16* __restrict__ WsL) {
    __shared__ float t[32][33];
    int zi = blockIdx.z;
    const float* src = (zi == 0) ? Wg : Ws + (size_t)(zi - 1) * CC * CC;
    __nv_bfloat16* dh = (zi == 0) ? WgH : WsH + (size_t)(zi - 1) * CC * CC;
    __nv_bfloat16* dl = (zi == 0) ? WgL : WsL + (size_t)(zi - 1) * CC * CC;
    int bx = blockIdx.x * 32, by = blockIdx.y * 32;
    int x = bx + threadIdx.x;
#pragma unroll
    for (int j = 0; j < 32; j += 8)
        t[threadIdx.y + j][threadIdx.x] = src[(size_t)(by + threadIdx.y + j) * CC + x];
    __syncthreads();
    int x2 = by + threadIdx.x;
#pragma unroll
    for (int j = 0; j < 32; j += 8) {
        float v = t[threadIdx.x][threadIdx.y + j];
        size_t o = (size_t)(bx + threadIdx.y + j) * CC + x2;
        __nv_bfloat16 h, l; split2(v, h, l);
        dh[o] = h; dl[o] = l;
    }
}

// ---------------- top-16 candidates + fp32 rescore + exact top-8 ----------------
__global__ __launch_bounds__(256) void topk_rescore_kernel() {
    __shared__ float sv[NUM_L];
    __shared__ float rv[256];
    __shared__ int   ri[256];
    __shared__ int   cand[16];
    __shared__ float cs[16];
    __shared__ float lrow[CC];
    int r = blockIdx.x, tid = threadIdx.x;
    const float* row = g_sim + (size_t)r * NUM_L;
    for (int c = tid; c < NUM_L; c += 256) sv[c] = row[c];
    __syncthreads();
    for (int t = 0; t < 16; t++) {
        float bv = -INFINITY; int bi = NUM_L;
        for (int c = tid; c < NUM_L; c += 256) {
            float v = sv[c];
            if (v > bv || (v == bv && c < bi)) { bv = v; bi = c; }
        }
        rv[tid] = bv; ri[tid] = bi;
        __syncthreads();
        for (int s = 128; s > 0; s >>= 1) {
            if (tid < s) {
                float v = rv[tid + s]; int i2 = ri[tid + s];
                if (v > rv[tid] || (v == rv[tid] && i2 < ri[tid])) { rv[tid] = v; ri[tid] = i2; }
            }
            __syncthreads();
        }
        if (tid == 0) { cand[t] = ri[0]; sv[ri[0]] = -INFINITY; }
        __syncthreads();
    }
    for (int d = tid; d < CC; d += 256)
        lrow[d] = __bfloat162float(g_LRh[(size_t)r * CC + d])
                + __bfloat162float(g_LRl[(size_t)r * CC + d]);
    __syncthreads();
    int wid = tid >> 5, lane = tid & 31;
    for (int c = wid; c < 16; c += 8) {
        size_t rr = (size_t)(cand[c] + NUM_L) * CC;
        float s = 0.f;
        for (int d = lane; d < CC; d += 32)
            s += lrow[d] * (__bfloat162float(g_LRh[rr + d]) + __bfloat162float(g_LRl[rr + d]));
#pragma unroll
        for (int o = 16; o; o >>= 1) s += __shfl_xor_sync(0xffffffffu, s, o);
        if (lane == 0) cs[c] = s;
    }
    __syncthreads();
    if (tid == 0) {
        unsigned used = 0;
        for (int t = 0; t < KSEL; t++) {
            float bv = -INFINITY; int bslot = 0, bidx = NUM_L;
            for (int c = 0; c < 16; c++) {
                if (used & (1u << c)) continue;
                if (cs[c] > bv || (cs[c] == bv && cand[c] < bidx)) {
                    bv = cs[c]; bidx = cand[c]; bslot = c;
                }
            }
            used |= 1u << bslot;
            g_idx[r * KSEL + t] = bidx;
        }
    }
}

// ---------------- CSR build ----------------
__global__ void zero_deg_kernel() {
    int i = blockIdx.x * 256 + threadIdx.x;
    if (i < NUM_L) g_deg[i] = 0;
}
__global__ void count_deg_kernel() {
    int e = blockIdx.x * 256 + threadIdx.x;
    if (e < NUM_L * KSEL) atomicAdd(&g_deg[g_idx[e]], 1);
}
__global__ __launch_bounds__(512) void scan_off_kernel() {
    __shared__ int ss[512];
    int tid = threadIdx.x;
    int base = tid * 8;
    int loc[8]; int s = 0;
#pragma unroll
    for (int i = 0; i < 8; i++) { loc[i] = s; s += g_deg[base + i]; }
    ss[tid] = s; __syncthreads();
    for (int d = 1; d < 512; d <<= 1) {
        int v = (tid >= d) ? ss[tid - d] : 0;
        __syncthreads();
        ss[tid] += v;
        __syncthreads();
    }
    int excl = ss[tid] - s;
#pragma unroll
    for (int i = 0; i < 8; i++) g_off[base + i] = excl + loc[i];
    if (tid == 511) g_off[NUM_L] = ss[511];
}
__global__ void init_cursor_kernel() {
    int i = blockIdx.x * 256 + threadIdx.x;
    if (i < NUM_L) g_deg[i] = g_off[i];
}
__global__ void fill_atomic_kernel() {
    int e = blockIdx.x * 256 + threadIdx.x;
    if (e < NUM_L * KSEL) {
        int pos = atomicAdd(&g_deg[g_idx[e]], 1);
        g_elist[pos] = e;
    }
}
__global__ void sort_convert_kernel() {
    int j = blockIdx.x * 256 + threadIdx.x;
    if (j >= NUM_L) return;
    int e0 = g_off[j], e1 = g_off[j + 1];
    for (int i = e0 + 1; i < e1; i++) {
        int key = g_elist[i];
        int k = i - 1;
        while (k >= e0 && g_elist[k] > key) { g_elist[k + 1] = g_elist[k]; k--; }
        g_elist[k + 1] = key;
    }
    for (int i = e0; i < e1; i++) g_elist[i] >>= 3;
}

// ---------------- x init ----------------
__global__ void init_x_kernel(const float* __restrict__ l, const float* __restrict__ r) {
    int i = blockIdx.x * 256 + threadIdx.x;
    if (i < NUM_L * CC) {
        split2(l[i], g_xh[i], g_xl[i]);
        split2(r[i], g_xh[NUM_L * CC + i], g_xl[NUM_L * CC + i]);
    }
}

// ---------------- fused bias + act + split ----------------
__device__ __forceinline__ void store_x(int n, int d, float v, int elu) {
    if (elu) v = v > 0.f ? v : expm1f(v);
    size_t o = (size_t)n * CC + d;
    split2(v, g_xh[o], g_xl[o]);
}

// ---------------- 12-channel block reductions ----------------
__device__ __forceinline__ void block_max12(float* lv, float* red, float* outp, int tid) {
#pragma unroll
    for (int h = 0; h < HH; h++)
#pragma unroll
        for (int o = 16; o; o >>= 1)
            lv[h] = fmaxf(lv[h], __shfl_xor_sync(0xffffffffu, lv[h], o));
    if ((tid & 31) == 0)
#pragma unroll
        for (int h = 0; h < HH; h++) red[(tid >> 5) * HH + h] = lv[h];
    __syncthreads();
    if (tid < HH) {
        float v = red[tid];
#pragma unroll
        for (int w = 1; w < 8; w++) v = fmaxf(v, red[w * HH + tid]);
        outp[tid] = v;
    }
    __syncthreads();
}
__device__ __forceinline__ void block_sum12(float* lv, float* red, float* outp, int tid) {
#pragma unroll
    for (int h = 0; h < HH; h++)
#pragma unroll
        for (int o = 16; o; o >>= 1)
            lv[h] += __shfl_xor_sync(0xffffffffu, lv[h], o);
    if ((tid & 31) == 0)
#pragma unroll
        for (int h = 0; h < HH; h++) red[(tid >> 5) * HH + h] = lv[h];
    __syncthreads();
    if (tid < HH) {
        float v = red[tid];
#pragma unroll
        for (int w = 1; w < 8; w++) v += red[w * HH + tid];
        outp[tid] = v;
    }
    __syncthreads();
}

// ---------------- GAT aggregation + act, graph 1 ----------------
__global__ __launch_bounds__(256) void agg1_kernel(const float* __restrict__ bias, int elu) {
    int n = blockIdx.x, tid = threadIdx.x;
    if (n < NUM_L) {   // left nodes: self loop only -> out = act(z + b)
        for (int d = tid; d < CC; d += 256)
            store_x(n, d, g_z[(size_t)n * CC + d] + bias[d], elu);
        return;
    }
    __shared__ float s_er[HH], s_m[HH], s_sum[HH], s_inv[HH];
    __shared__ float red[8 * HH];
    int j = n - NUM_L;
    int e0 = g_off[j], e1 = g_off[j + 1];
    int deg = e1 - e0;
    if (tid < HH) s_er[tid] = g_er[n * HH + tid];
    __syncthreads();

    float lv[HH];
#pragma unroll
    for (int h = 0; h < HH; h++) lv[h] = -INFINITY;
    for (int t = tid; t < deg + 1; t += 256) {
        int src = (t < deg) ? g_elist[e0 + t] : n;
        const float* elp = g_el + src * HH;
#pragma unroll
        for (int h = 0; h < HH; h++) lv[h] = fmaxf(lv[h], lrelu(elp[h] + s_er[h]));
    }
    block_max12(lv, red, s_m, tid);

#pragma unroll
    for (int h = 0; h < HH; h++) lv[h] = 0.f;
    for (int t = tid; t < deg + 1; t += 256) {
        int src = (t < deg) ? g_elist[e0 + t] : n;
        const float* elp = g_el + src * HH;
#pragma unroll
        for (int h = 0; h < HH; h++) lv[h] += expf(lrelu(elp[h] + s_er[h]) - s_m[h]);
    }
    block_sum12(lv, red, s_sum, tid);
    if (tid < HH) s_inv[tid] = 1.f / s_sum[tid];
    __syncthreads();

    for (int d = tid; d < CC; d += 256) {
        int h = d >> 6;
        float m = s_m[h], inv = s_inv[h], erh = s_er[h];
        float acc = expf(lrelu(g_el[n * HH + h] + erh) - m) * inv * g_z[(size_t)n * CC + d];
        for (int e = e0; e < e1; e++) {
            int src = g_elist[e];
            acc += expf(lrelu(g_el[src * HH + h] + erh) - m) * inv * g_z[(size_t)src * CC + d];
        }
        store_x(n, d, acc + bias[d], elu);
    }
}

// ---------------- GAT aggregation + act, graph 2 ----------------
__global__ __launch_bounds__(256) void agg2_kernel(const float* __restrict__ bias,
                                                   int elu, int final_, float* outp) {
    int n = blockIdx.x, tid = threadIdx.x;
    if (n & (PPAT - 1)) {
        if (final_) return;   // last layer: non-image outputs never read
        for (int d = tid; d < CC; d += 256)
            store_x(n, d, g_z[(size_t)n * CC + d] + bias[d], elu);
        return;
    }
    __shared__ float s_er[HH], s_m[HH], s_sum[HH], s_inv[HH];
    __shared__ float s_w[PPAT * HH];
    __shared__ float red[8 * HH];
    if (tid < HH) s_er[tid] = g_er[n * HH + tid];
    __syncthreads();

    int src = n + tid;
    float ev[HH];
    const float* elp = g_el + src * HH;
#pragma unroll
    for (int h = 0; h < HH; h++) ev[h] = lrelu(elp[h] + s_er[h]);

    float lv[HH];
#pragma unroll
    for (int h = 0; h < HH; h++) lv[h] = ev[h];
    block_max12(lv, red, s_m, tid);

    float mult = (tid == 0) ? 2.f : 1.f;   // duplicated self edge
    float ex[HH];
#pragma unroll
    for (int h = 0; h < HH; h++) { ex[h] = expf(ev[h] - s_m[h]) * mult; lv[h] = ex[h]; }
    block_sum12(lv, red, s_sum, tid);
    if (tid < HH) s_inv[tid] = 1.f / s_sum[tid];
    __syncthreads();
#pragma unroll
    for (int h = 0; h < HH; h++) s_w[tid * HH + h] = ex[h] * s_inv[h];
    __syncthreads();

    for (int d = tid; d < CC; d += 256) {
        int h = d >> 6;
        float acc = 0.f;
        for (int i = 0; i < PPAT; i++)
            acc += s_w[i * HH + h] * g_z[(size_t)(n + i) * CC + d];
        float v = acc + bias[d];
        if (final_) {
            if (elu) v = v > 0.f ? v : expm1f(v);
            outp[(size_t)(n / PPAT) * CC + d] = v;
        } else {
            store_x(n, d, v, elu);
        }
    }
}

// ---------------- launch ----------------
extern "C" void kernel_launch(void* const* d_in, const int* in_sizes, int n_in,
                              void* d_out, int out_size) {
    (void)in_sizes; (void)n_in; (void)out_size;
    const float* l_feat = (const float*)d_in[0];
    const float* r_feat = (const float*)d_in[1];
    const float* Wg     = (const float*)d_in[2];
    const float* Ws     = (const float*)d_in[3];
    const float* a_src  = (const float*)d_in[4];
    const float* a_dst  = (const float*)d_in[5];
    const float* b      = (const float*)d_in[6];
    float* out = (float*)d_out;

    cudaFuncSetAttribute(gemm_mma<3, 2>, cudaFuncAttributeMaxDynamicSharedMemorySize, GEMM_SMEM);
    cudaFuncSetAttribute(gemm_mma<1, 4>, cudaFuncAttributeMaxDynamicSharedMemorySize, GEMM_SMEM);

    __nv_bfloat16 *pWgh, *pWgl, *pWsh, *pWsl, *pxh, *pxl, *pLRh, *pLRl;
    float *pSim, *pZ;
    cudaGetSymbolAddress((void**)&pWgh, g_Wgt_h);
    cudaGetSymbolAddress((void**)&pWgl, g_Wgt_l);
    cudaGetSymbolAddress((void**)&pWsh, g_Wst_h);
    cudaGetSymbolAddress((void**)&pWsl, g_Wst_l);
    cudaGetSymbolAddress((void**)&pxh,  g_xh);
    cudaGetSymbolAddress((void**)&pxl,  g_xl);
    cudaGetSymbolAddress((void**)&pLRh, g_LRh);
    cudaGetSymbolAddress((void**)&pLRl, g_LRl);
    cudaGetSymbolAddress((void**)&pSim, g_sim);
    cudaGetSymbolAddress((void**)&pZ,   g_z);

    transpose_split_all<<<dim3(24, 24, 5), dim3(32, 8)>>>(Wg, Ws, pWgh, pWgl, pWsh, pWsl);
    init_x_kernel<<<NUM_L * CC / 256, 256>>>(l_feat, r_feat);

    // GraphGenerator: LR projection, hi-only sim (4-stage), top-16 + rescore
    gemm_mma<3, 2><<<dim3(CC / 128, NTOT / 128), 256, GEMM_SMEM>>>(
        pxh, pxl, pWgh, pWgl, nullptr, pLRh, pLRl, nullptr, nullptr, NTOT, CC, CC, 1);
    gemm_mma<1, 4><<<dim3(NUM_L / 128, NUM_L / 128), 256, GEMM_SMEM>>>(
        pLRh, pLRl, pLRh + (size_t)NUM_L * CC, pLRl + (size_t)NUM_L * CC,
        pSim, nullptr, nullptr, nullptr, nullptr, NUM_L, NUM_L, CC, 0);
    topk_rescore_kernel<<<NUM_L, 256>>>();

    // CSR for graph 1
    zero_deg_kernel<<<16, 256>>>();
    count_deg_kernel<<<NUM_L * KSEL / 256, 256>>>();
    scan_off_kernel<<<1, 512>>>();
    init_cursor_kernel<<<16, 256>>>();
    fill_atomic_kernel<<<NUM_L * KSEL / 256, 256>>>();
    sort_convert_kernel<<<16, 256>>>();

    for (int g = 0; g < 2; g++) {
        for (int l = 0; l < NLAYERS; l++) {
            gemm_mma<3, 2><<<dim3(CC / 128, NTOT / 128), 256, GEMM_SMEM>>>(
                pxh, pxl, pWsh + (size_t)l * CC * CC, pWsl + (size_t)l * CC * CC,
                pZ, nullptr, nullptr,
                a_src + l * HH * DDIM, a_dst + l * HH * DDIM, NTOT, CC, CC, 0);
            int elu = (l < NLAYERS - 1) ? 1 : 0;
            if (g == 0) agg1_kernel<<<NTOT, 256>>>(b + l * CC, elu);
            else        agg2_kernel<<<NTOT, 256>>>(b + l * CC, elu,
                                                   (l == NLAYERS - 1) ? 1 : 0, out);
        }
    }
}

// round 17
// speedup vs baseline: 1.1243x; 1.0402x over previous
#include <cuda_runtime.h>
#include <cuda_bf16.h>
#include <math.h>
#include <stdint.h>

#define NUM_L   4096
#define NTOT    8192
#define CC      768
#define HH      12
#define DDIM    64
#define KSEL    8
#define PPAT    256
#define NLAYERS 4
#define NEG_SLOPE 0.2f

// ---------------- device scratch ----------------
__device__ float g_sim[NUM_L * NUM_L];          // 64 MB
__device__ int   g_idx[NUM_L * KSEL];
__device__ float g_z [NTOT * CC];
__device__ float g_el[NTOT * HH];
__device__ float g_er[NTOT * HH];
__device__ __nv_bfloat16 g_xh[NTOT * CC], g_xl[NTOT * CC];
__device__ __nv_bfloat16 g_LRh[NTOT * CC], g_LRl[NTOT * CC];
__device__ __nv_bfloat16 g_Wgt_h[CC * CC], g_Wgt_l[CC * CC];
__device__ __nv_bfloat16 g_Wst_h[NLAYERS * CC * CC], g_Wst_l[NLAYERS * CC * CC];
__device__ int   g_deg[NUM_L];
__device__ int   g_off[NUM_L + 1];
__device__ int   g_elist[NUM_L * KSEL];

__device__ __forceinline__ float lrelu(float x) { return x >= 0.f ? x : NEG_SLOPE * x; }

__device__ __forceinline__ uint32_t smem_u32(const void* p) {
    uint32_t a;
    asm("{ .reg .u64 t; cvta.to.shared.u64 t, %1; cvt.u32.u64 %0, t; }" : "=r"(a) : "l"(p));
    return a;
}
__device__ __forceinline__ void split2(float v, __nv_bfloat16& h, __nv_bfloat16& l) {
    h = __float2bfloat16(v);
    l = __float2bfloat16(v - __bfloat162float(h));
}

// ======================= mma.sync bf16 GEMM =======================
// C = A*B^T; A,B bf16 (hi,lo) pairs, K-contiguous. NMMA=3: full split precision.
// NMMA=1: hi*hi only, 2 smem tiles -> NST=4 stages in the same smem budget.
// Optional fused epilogue: el/er per-row head dots vs as_/ad_ (layer GEMMs).
#define SA      40
#define TILE_B  (128 * SA * 2)          // 10240 B per 128x32 tile
#define GEMM_SMEM 81920                 // 2 stages x 4 tiles == 4 stages x 2 tiles

#define CP16(s, g) \
    asm volatile("cp.async.cg.shared.global [%0], [%1], 16;" :: "r"(s), "l"(g))
#define CP_COMMIT() asm volatile("cp.async.commit_group;" ::: "memory")

#define LDSM4(r0, r1, r2, r3, a) \
    asm volatile("ldmatrix.sync.aligned.m8n8.x4.shared.b16 {%0,%1,%2,%3}, [%4];" \
                 : "=r"(r0), "=r"(r1), "=r"(r2), "=r"(r3) : "r"(a))

#define MMA16816(d, a, b) \
    asm volatile("mma.sync.aligned.m16n8k16.row.col.f32.bf16.bf16.f32 " \
                 "{%0,%1,%2,%3},{%4,%5,%6,%7},{%8,%9},{%0,%1,%2,%3};" \
                 : "+f"((d)[0]), "+f"((d)[1]), "+f"((d)[2]), "+f"((d)[3]) \
                 : "r"((a)[0]), "r"((a)[1]), "r"((a)[2]), "r"((a)[3]), \
                   "r"((b)[0]), "r"((b)[1]))

template<int NMMA, int NST>
__global__ void __launch_bounds__(256, 2) gemm_mma(
    const __nv_bfloat16* __restrict__ Ah, const __nv_bfloat16* __restrict__ Al,
    const __nv_bfloat16* __restrict__ Bh, const __nv_bfloat16* __restrict__ Bl,
    float* __restrict__ Cf, __nv_bfloat16* __restrict__ Ch, __nv_bfloat16* __restrict__ Cl,
    const float* __restrict__ as_, const float* __restrict__ ad_,
    int M, int N, int K, int splitout)
{
    extern __shared__ __align__(16) char dsm[];
    __shared__ float s_red[128][2][2];
    const int NTILES = (NMMA == 1) ? 2 : 4;
    const int STB = NTILES * TILE_B;
    // Wait depth: NST=2 issues at loop BOTTOM (pending at wait: {c, c+1}) -> 1.
    // NST=4 issues at loop TOP after the wait (pending: {c, c+1, c+2}) -> NST-2.
    constexpr int WG = (NST == 2) ? 1 : (NST - 2);
    const uint32_t sbase = smem_u32(dsm);
    const int tid = threadIdx.x;
    const int wid = tid >> 5, lane = tid & 31;
    const int wm = wid & 1, wn = wid >> 1;
    const int bm = blockIdx.y * 128, bn = blockIdx.x * 128;

    const __nv_bfloat16* srcs[4] = {
        Ah + (size_t)bm * K, Al + (size_t)bm * K,
        Bh + (size_t)bn * K, Bl + (size_t)bn * K };

    const int r0 = tid >> 2, c0 = tid & 3;
    const int r1 = (tid + 256) >> 2, c1 = (tid + 256) & 3;

    const int lj = lane >> 3, lr = lane & 7;
    const uint32_t aoff = (uint32_t)((((lj & 1) * 8 + lr) * SA + (lj >> 1) * 8) * 2);
    const uint32_t boff = (uint32_t)((((lj >> 1) * 8 + lr) * SA + (lj & 1) * 8) * 2);

    float acc[4][4][4];
#pragma unroll
    for (int i = 0; i < 4; i++)
#pragma unroll
        for (int j = 0; j < 4; j++)
#pragma unroll
            for (int k = 0; k < 4; k++) acc[i][j][k] = 0.f;

    const int nc = K >> 5;
    const int NPRO = (NST == 2) ? 2 : (NST - 1);

#pragma unroll
    for (int s = 0; s < NPRO; s++) {
        const uint32_t st = sbase + s * STB;
        const int kb = s * 32;
#pragma unroll
        for (int t = 0; t < 4; t++) {
            if (NMMA == 1 && (t & 1)) continue;
            const int slot = (NMMA == 1) ? (t >> 1) : t;
            const __nv_bfloat16* gp = srcs[t] + kb;
            CP16(st + slot * TILE_B + r0 * (SA * 2) + c0 * 16, gp + (size_t)r0 * K + c0 * 8);
            CP16(st + slot * TILE_B + r1 * (SA * 2) + c1 * 16, gp + (size_t)r1 * K + c1 * 8);
        }
        CP_COMMIT();
    }

    for (int c = 0; c < nc; c++) {
        asm volatile("cp.async.wait_group %0;" :: "n"(WG) : "memory");
        __syncthreads();
        if (NST > 2) {
            // stage c+NST-1 -> buffer (c-1)%NST, freed by the sync above
            if (c + NST - 1 < nc) {
                const uint32_t st2 = sbase + ((c + NST - 1) % NST) * STB;
                const int kb = (c + NST - 1) * 32;
#pragma unroll
                for (int t = 0; t < 4; t++) {
                    if (NMMA == 1 && (t & 1)) continue;
                    const int slot = (NMMA == 1) ? (t >> 1) : t;
                    const __nv_bfloat16* gp = srcs[t] + kb;
                    CP16(st2 + slot * TILE_B + r0 * (SA * 2) + c0 * 16, gp + (size_t)r0 * K + c0 * 8);
                    CP16(st2 + slot * TILE_B + r1 * (SA * 2) + c1 * 16, gp + (size_t)r1 * K + c1 * 8);
                }
            }
            CP_COMMIT();
        }

        const uint32_t st = sbase + (c % NST) * STB;
        const uint32_t sAh = st + (uint32_t)(wm * 64 * SA * 2);
        const uint32_t sAl = st + 1 * TILE_B + (uint32_t)(wm * 64 * SA * 2);
        const uint32_t sBh = st + ((NMMA == 1) ? 1 : 2) * TILE_B + (uint32_t)(wn * 32 * SA * 2);
        const uint32_t sBl = st + 3 * TILE_B + (uint32_t)(wn * 32 * SA * 2);
#pragma unroll
        for (int kk = 0; kk < 2; kk++) {
            const uint32_t kadd = kk * 32;
            uint32_t bh[2][4], bl[2][4];
#pragma unroll
            for (int np = 0; np < 2; np++) {
                const uint32_t noff = (uint32_t)(np * 16 * SA * 2) + kadd;
                LDSM4(bh[np][0], bh[np][1], bh[np][2], bh[np][3], sBh + noff + boff);
                if (NMMA == 3)
                    LDSM4(bl[np][0], bl[np][1], bl[np][2], bl[np][3], sBl + noff + boff);
            }
#pragma unroll
            for (int mt = 0; mt < 4; mt++) {
                uint32_t ah[4], al[4];
                const uint32_t moff = (uint32_t)(mt * 16 * SA * 2) + kadd;
                LDSM4(ah[0], ah[1], ah[2], ah[3], sAh + moff + aoff);
                if (NMMA == 3)
                    LDSM4(al[0], al[1], al[2], al[3], sAl + moff + aoff);
#pragma unroll
                for (int nt = 0; nt < 4; nt++) {
                    const uint32_t* bhf = &bh[nt >> 1][(nt & 1) * 2];
                    MMA16816(acc[mt][nt], ah, bhf);
                    if (NMMA == 3) {
                        const uint32_t* blf = &bl[nt >> 1][(nt & 1) * 2];
                        MMA16816(acc[mt][nt], ah, blf);
                        MMA16816(acc[mt][nt], al, bhf);
                    }
                }
            }
        }
        if (NST == 2) {
            __syncthreads();
            if (c + 2 < nc) {
                const int kb = (c + 2) * 32;
#pragma unroll
                for (int t = 0; t < 4; t++) {
                    if (NMMA == 1 && (t & 1)) continue;
                    const int slot = (NMMA == 1) ? (t >> 1) : t;
                    const __nv_bfloat16* gp = srcs[t] + kb;
                    CP16(st + slot * TILE_B + r0 * (SA * 2) + c0 * 16, gp + (size_t)r0 * K + c0 * 8);
                    CP16(st + slot * TILE_B + r1 * (SA * 2) + c1 * 16, gp + (size_t)r1 * K + c1 * 8);
                }
            }
            CP_COMMIT();
        }
    }

    const int er = lane >> 2, ec = (lane & 3) * 2;

    // ---- C store ----
#pragma unroll
    for (int mt = 0; mt < 4; mt++) {
        const int row = bm + wm * 64 + mt * 16 + er;
#pragma unroll
        for (int nt = 0; nt < 4; nt++) {
            const int col = bn + wn * 32 + nt * 8 + ec;
            if (!splitout) {
                float2* p0 = (float2*)(Cf + (size_t)row * N + col);
                float2* p1 = (float2*)(Cf + (size_t)(row + 8) * N + col);
                *p0 = make_float2(acc[mt][nt][0], acc[mt][nt][1]);
                *p1 = make_float2(acc[mt][nt][2], acc[mt][nt][3]);
            } else {
#pragma unroll
                for (int half = 0; half < 2; half++) {
                    const size_t o = (size_t)(row + half * 8) * N + col;
                    __nv_bfloat16 h0, l0, h1, l1;
                    split2(acc[mt][nt][half * 2 + 0], h0, l0);
                    split2(acc[mt][nt][half * 2 + 1], h1, l1);
                    __nv_bfloat162 hv; hv.x = h0; hv.y = h1;
                    __nv_bfloat162 lv2; lv2.x = l0; lv2.y = l1;
                    *(__nv_bfloat162*)(Ch + o) = hv;
                    *(__nv_bfloat162*)(Cl + o) = lv2;
                }
            }
        }
    }

    // ---- fused el/er epilogue (layer GEMMs; N == 768, heads of 64 cols) ----
    if (as_ != nullptr) {
        const int h    = (bn + wn * 32) >> 6;
        const int hl   = wn >> 1;
        const int cih0 = (wn & 1) * 32;
        float elv[4][2], erv[4][2];
#pragma unroll
        for (int mt = 0; mt < 4; mt++) { elv[mt][0] = elv[mt][1] = erv[mt][0] = erv[mt][1] = 0.f; }
#pragma unroll
        for (int nt = 0; nt < 4; nt++) {
            const int cih = cih0 + nt * 8 + ec;
            const float a0 = as_[h * DDIM + cih], a1 = as_[h * DDIM + cih + 1];
            const float d0 = ad_[h * DDIM + cih], d1 = ad_[h * DDIM + cih + 1];
#pragma unroll
            for (int mt = 0; mt < 4; mt++) {
                elv[mt][0] += acc[mt][nt][0] * a0 + acc[mt][nt][1] * a1;
                elv[mt][1] += acc[mt][nt][2] * a0 + acc[mt][nt][3] * a1;
                erv[mt][0] += acc[mt][nt][0] * d0 + acc[mt][nt][1] * d1;
                erv[mt][1] += acc[mt][nt][2] * d0 + acc[mt][nt][3] * d1;
            }
        }
#pragma unroll
        for (int mt = 0; mt < 4; mt++)
#pragma unroll
            for (int hf = 0; hf < 2; hf++) {
#pragma unroll
                for (int o = 1; o <= 2; o <<= 1) {
                    elv[mt][hf] += __shfl_xor_sync(0xffffffffu, elv[mt][hf], o);
                    erv[mt][hf] += __shfl_xor_sync(0xffffffffu, erv[mt][hf], o);
                }
            }
        __syncthreads();
        if ((wn & 1) == 0 && (lane & 3) == 0) {
#pragma unroll
            for (int mt = 0; mt < 4; mt++)
#pragma unroll
                for (int hf = 0; hf < 2; hf++) {
                    const int r = wm * 64 + mt * 16 + er + hf * 8;
                    s_red[r][hl][0] = elv[mt][hf];
                    s_red[r][hl][1] = erv[mt][hf];
                }
        }
        __syncthreads();
        if ((wn & 1) == 1 && (lane & 3) == 0) {
#pragma unroll
            for (int mt = 0; mt < 4; mt++)
#pragma unroll
                for (int hf = 0; hf < 2; hf++) {
                    const int r = wm * 64 + mt * 16 + er + hf * 8;
                    g_el[(size_t)(bm + r) * HH + h] = s_red[r][hl][0] + elv[mt][hf];
                    g_er[(size_t)(bm + r) * HH + h] = s_red[r][hl][1] + erv[mt][hf];
                }
        }
    }
}

// ---------------- batched 768x768 transpose + split ----------------
__global__ void transpose_split_all(const float* __restrict__ Wg,
                                    const float* __restrict__ Ws,
                                    __nv_bfloat16* __restrict__ WgH, __nv_bfloat16* __restrict__ WgL,
                                    __nv_bfloat16* __restrict__ WsH, __nv_bfloat16* __restrict__ WsL) {
    __shared__ float t[32][33];
    int zi = blockIdx.z;
    const float* src = (zi == 0) ? Wg : Ws + (size_t)(zi - 1) * CC * CC;
    __nv_bfloat16* dh = (zi == 0) ? WgH : WsH + (size_t)(zi - 1) * CC * CC;
    __nv_bfloat16* dl = (zi == 0) ? WgL : WsL + (size_t)(zi - 1) * CC * CC;
    int bx = blockIdx.x * 32, by = blockIdx.y * 32;
    int x = bx + threadIdx.x;
#pragma unroll
    for (int j = 0; j < 32; j += 8)
        t[threadIdx.y + j][threadIdx.x] = src[(size_t)(by + threadIdx.y + j) * CC + x];
    __syncthreads();
    int x2 = by + threadIdx.x;
#pragma unroll
    for (int j = 0; j < 32; j += 8) {
        float v = t[threadIdx.x][threadIdx.y + j];
        size_t o = (size_t)(bx + threadIdx.y + j) * CC + x2;
        __nv_bfloat16 h, l; split2(v, h, l);
        dh[o] = h; dl[o] = l;
    }
}

// ---------------- top-16 candidates + fp32 rescore + exact top-8 ----------------
__global__ __launch_bounds__(256) void topk_rescore_kernel() {
    __shared__ float sv[NUM_L];
    __shared__ float rv[256];
    __shared__ int   ri[256];
    __shared__ int   cand[16];
    __shared__ float cs[16];
    __shared__ float lrow[CC];
    int r = blockIdx.x, tid = threadIdx.x;
    const float* row = g_sim + (size_t)r * NUM_L;
    for (int c = tid; c < NUM_L; c += 256) sv[c] = row[c];
    __syncthreads();
    for (int t = 0; t < 16; t++) {
        float bv = -INFINITY; int bi = NUM_L;
        for (int c = tid; c < NUM_L; c += 256) {
            float v = sv[c];
            if (v > bv || (v == bv && c < bi)) { bv = v; bi = c; }
        }
        rv[tid] = bv; ri[tid] = bi;
        __syncthreads();
        for (int s = 128; s > 0; s >>= 1) {
            if (tid < s) {
                float v = rv[tid + s]; int i2 = ri[tid + s];
                if (v > rv[tid] || (v == rv[tid] && i2 < ri[tid])) { rv[tid] = v; ri[tid] = i2; }
            }
            __syncthreads();
        }
        if (tid == 0) { cand[t] = ri[0]; sv[ri[0]] = -INFINITY; }
        __syncthreads();
    }
    for (int d = tid; d < CC; d += 256)
        lrow[d] = __bfloat162float(g_LRh[(size_t)r * CC + d])
                + __bfloat162float(g_LRl[(size_t)r * CC + d]);
    __syncthreads();
    int wid = tid >> 5, lane = tid & 31;
    for (int c = wid; c < 16; c += 8) {
        size_t rr = (size_t)(cand[c] + NUM_L) * CC;
        float s = 0.f;
        for (int d = lane; d < CC; d += 32)
            s += lrow[d] * (__bfloat162float(g_LRh[rr + d]) + __bfloat162float(g_LRl[rr + d]));
#pragma unroll
        for (int o = 16; o; o >>= 1) s += __shfl_xor_sync(0xffffffffu, s, o);
        if (lane == 0) cs[c] = s;
    }
    __syncthreads();
    if (tid == 0) {
        unsigned used = 0;
        for (int t = 0; t < KSEL; t++) {
            float bv = -INFINITY; int bslot = 0, bidx = NUM_L;
            for (int c = 0; c < 16; c++) {
                if (used & (1u << c)) continue;
                if (cs[c] > bv || (cs[c] == bv && cand[c] < bidx)) {
                    bv = cs[c]; bidx = cand[c]; bslot = c;
                }
            }
            used |= 1u << bslot;
            g_idx[r * KSEL + t] = bidx;
        }
    }
}

// ---------------- CSR build ----------------
__global__ void zero_deg_kernel() {
    int i = blockIdx.x * 256 + threadIdx.x;
    if (i < NUM_L) g_deg[i] = 0;
}
__global__ void count_deg_kernel() {
    int e = blockIdx.x * 256 + threadIdx.x;
    if (e < NUM_L * KSEL) atomicAdd(&g_deg[g_idx[e]], 1);
}
__global__ __launch_bounds__(512) void scan_off_kernel() {
    __shared__ int ss[512];
    int tid = threadIdx.x;
    int base = tid * 8;
    int loc[8]; int s = 0;
#pragma unroll
    for (int i = 0; i < 8; i++) { loc[i] = s; s += g_deg[base + i]; }
    ss[tid] = s; __syncthreads();
    for (int d = 1; d < 512; d <<= 1) {
        int v = (tid >= d) ? ss[tid - d] : 0;
        __syncthreads();
        ss[tid] += v;
        __syncthreads();
    }
    int excl = ss[tid] - s;
#pragma unroll
    for (int i = 0; i < 8; i++) g_off[base + i] = excl + loc[i];
    if (tid == 511) g_off[NUM_L] = ss[511];
}
__global__ void init_cursor_kernel() {
    int i = blockIdx.x * 256 + threadIdx.x;
    if (i < NUM_L) g_deg[i] = g_off[i];
}
__global__ void fill_atomic_kernel() {
    int e = blockIdx.x * 256 + threadIdx.x;
    if (e < NUM_L * KSEL) {
        int pos = atomicAdd(&g_deg[g_idx[e]], 1);
        g_elist[pos] = e;
    }
}
__global__ void sort_convert_kernel() {
    int j = blockIdx.x * 256 + threadIdx.x;
    if (j >= NUM_L) return;
    int e0 = g_off[j], e1 = g_off[j + 1];
    for (int i = e0 + 1; i < e1; i++) {
        int key = g_elist[i];
        int k = i - 1;
        while (k >= e0 && g_elist[k] > key) { g_elist[k + 1] = g_elist[k]; k--; }
        g_elist[k + 1] = key;
    }
    for (int i = e0; i < e1; i++) g_elist[i] >>= 3;
}

// ---------------- x init ----------------
__global__ void init_x_kernel(const float* __restrict__ l, const float* __restrict__ r) {
    int i = blockIdx.x * 256 + threadIdx.x;
    if (i < NUM_L * CC) {
        split2(l[i], g_xh[i], g_xl[i]);
        split2(r[i], g_xh[NUM_L * CC + i], g_xl[NUM_L * CC + i]);
    }
}

// ---------------- fused bias + act + split ----------------
__device__ __forceinline__ void store_x(int n, int d, float v, int elu) {
    if (elu) v = v > 0.f ? v : expm1f(v);
    size_t o = (size_t)n * CC + d;
    split2(v, g_xh[o], g_xl[o]);
}

// ---------------- 12-channel block reductions ----------------
__device__ __forceinline__ void block_max12(float* lv, float* red, float* outp, int tid) {
#pragma unroll
    for (int h = 0; h < HH; h++)
#pragma unroll
        for (int o = 16; o; o >>= 1)
            lv[h] = fmaxf(lv[h], __shfl_xor_sync(0xffffffffu, lv[h], o));
    if ((tid & 31) == 0)
#pragma unroll
        for (int h = 0; h < HH; h++) red[(tid >> 5) * HH + h] = lv[h];
    __syncthreads();
    if (tid < HH) {
        float v = red[tid];
#pragma unroll
        for (int w = 1; w < 8; w++) v = fmaxf(v, red[w * HH + tid]);
        outp[tid] = v;
    }
    __syncthreads();
}
__device__ __forceinline__ void block_sum12(float* lv, float* red, float* outp, int tid) {
#pragma unroll
    for (int h = 0; h < HH; h++)
#pragma unroll
        for (int o = 16; o; o >>= 1)
            lv[h] += __shfl_xor_sync(0xffffffffu, lv[h], o);
    if ((tid & 31) == 0)
#pragma unroll
        for (int h = 0; h < HH; h++) red[(tid >> 5) * HH + h] = lv[h];
    __syncthreads();
    if (tid < HH) {
        float v = red[tid];
#pragma unroll
        for (int w = 1; w < 8; w++) v += red[w * HH + tid];
        outp[tid] = v;
    }
    __syncthreads();
}

// ---------------- GAT aggregation + act, graph 1 ----------------
// Final aggregation uses per-(edge, head) alphas precomputed once per block in
// smem (64-edge chunks), removing the per-feature expf recomputation.
#define ECHUNK 64
__global__ __launch_bounds__(256) void agg1_kernel(const float* __restrict__ bias, int elu) {
    int n = blockIdx.x, tid = threadIdx.x;
    if (n < NUM_L) {   // left nodes: self loop only -> out = act(z + b)
        for (int d = tid; d < CC; d += 256)
            store_x(n, d, g_z[(size_t)n * CC + d] + bias[d], elu);
        return;
    }
    __shared__ float s_er[HH], s_m[HH], s_sum[HH], s_inv[HH], s_self[HH];
    __shared__ float red[8 * HH];
    __shared__ float s_al[ECHUNK * HH];
    __shared__ int   s_srcs[ECHUNK];
    int j = n - NUM_L;
    int e0 = g_off[j], e1 = g_off[j + 1];
    int deg = e1 - e0;
    if (tid < HH) s_er[tid] = g_er[n * HH + tid];
    __syncthreads();

    float lv[HH];
#pragma unroll
    for (int h = 0; h < HH; h++) lv[h] = -INFINITY;
    for (int t = tid; t < deg + 1; t += 256) {
        int src = (t < deg) ? g_elist[e0 + t] : n;
        const float* elp = g_el + src * HH;
#pragma unroll
        for (int h = 0; h < HH; h++) lv[h] = fmaxf(lv[h], lrelu(elp[h] + s_er[h]));
    }
    block_max12(lv, red, s_m, tid);

#pragma unroll
    for (int h = 0; h < HH; h++) lv[h] = 0.f;
    for (int t = tid; t < deg + 1; t += 256) {
        int src = (t < deg) ? g_elist[e0 + t] : n;
        const float* elp = g_el + src * HH;
#pragma unroll
        for (int h = 0; h < HH; h++) lv[h] += expf(lrelu(elp[h] + s_er[h]) - s_m[h]);
    }
    block_sum12(lv, red, s_sum, tid);
    if (tid < HH) {
        float inv = 1.f / s_sum[tid];
        s_inv[tid] = inv;
        s_self[tid] = expf(lrelu(g_el[n * HH + tid] + s_er[tid]) - s_m[tid]) * inv;
    }
    __syncthreads();

    // d_j = tid + j*256, head h0 + j*4 (CC == 3*256, DDIM == 64)
    const int h0 = tid >> 6;
    const float* zn = g_z + (size_t)n * CC;
    float acc0 = s_self[h0]     * zn[tid];
    float acc1 = s_self[h0 + 4] * zn[tid + 256];
    float acc2 = s_self[h0 + 8] * zn[tid + 512];

    for (int cs = e0; cs < e1; cs += ECHUNK) {
        int cnt = min(ECHUNK, e1 - cs);
        for (int idx = tid; idx < cnt * HH; idx += 256) {
            int e = idx / HH, h = idx - e * HH;
            int src = g_elist[cs + e];
            if (h == 0) s_srcs[e] = src;
            s_al[e * HH + h] =
                expf(lrelu(g_el[src * HH + h] + s_er[h]) - s_m[h]) * s_inv[h];
        }
        __syncthreads();
        for (int e = 0; e < cnt; e++) {
            const float* zp = g_z + (size_t)s_srcs[e] * CC;
            const float* al = s_al + e * HH;
            acc0 += al[h0]     * zp[tid];
            acc1 += al[h0 + 4] * zp[tid + 256];
            acc2 += al[h0 + 8] * zp[tid + 512];
        }
        __syncthreads();
    }
    store_x(n, tid,       acc0 + bias[tid],       elu);
    store_x(n, tid + 256, acc1 + bias[tid + 256], elu);
    store_x(n, tid + 512, acc2 + bias[tid + 512], elu);
}

// ---------------- GAT aggregation + act, graph 2 ----------------
__global__ __launch_bounds__(256) void agg2_kernel(const float* __restrict__ bias,
                                                   int elu, int final_, float* outp) {
    int n = blockIdx.x, tid = threadIdx.x;
    if (n & (PPAT - 1)) {
        if (final_) return;   // last layer: non-image outputs never read
        for (int d = tid; d < CC; d += 256)
            store_x(n, d, g_z[(size_t)n * CC + d] + bias[d], elu);
        return;
    }
    __shared__ float s_er[HH], s_m[HH], s_sum[HH], s_inv[HH];
    __shared__ float s_w[PPAT * HH];
    __shared__ float red[8 * HH];
    if (tid < HH) s_er[tid] = g_er[n * HH + tid];
    __syncthreads();

    int src = n + tid;
    float ev[HH];
    const float* elp = g_el + src * HH;
#pragma unroll
    for (int h = 0; h < HH; h++) ev[h] = lrelu(elp[h] + s_er[h]);

    float lv[HH];
#pragma unroll
    for (int h = 0; h < HH; h++) lv[h] = ev[h];
    block_max12(lv, red, s_m, tid);

    float mult = (tid == 0) ? 2.f : 1.f;   // duplicated self edge
    float ex[HH];
#pragma unroll
    for (int h = 0; h < HH; h++) { ex[h] = expf(ev[h] - s_m[h]) * mult; lv[h] = ex[h]; }
    block_sum12(lv, red, s_sum, tid);
    if (tid < HH) s_inv[tid] = 1.f / s_sum[tid];
    __syncthreads();
#pragma unroll
    for (int h = 0; h < HH; h++) s_w[tid * HH + h] = ex[h] * s_inv[h];
    __syncthreads();

    for (int d = tid; d < CC; d += 256) {
        int h = d >> 6;
        float acc = 0.f;
        for (int i = 0; i < PPAT; i++)
            acc += s_w[i * HH + h] * g_z[(size_t)(n + i) * CC + d];
        float v = acc + bias[d];
        if (final_) {
            if (elu) v = v > 0.f ? v : expm1f(v);
            outp[(size_t)(n / PPAT) * CC + d] = v;
        } else {
            store_x(n, d, v, elu);
        }
    }
}

// ---------------- launch ----------------
extern "C" void kernel_launch(void* const* d_in, const int* in_sizes, int n_in,
                              void* d_out, int out_size) {
    (void)in_sizes; (void)n_in; (void)out_size;
    const float* l_feat = (const float*)d_in[0];
    const float* r_feat = (const float*)d_in[1];
    const float* Wg     = (const float*)d_in[2];
    const float* Ws     = (const float*)d_in[3];
    const float* a_src  = (const float*)d_in[4];
    const float* a_dst  = (const float*)d_in[5];
    const float* b      = (const float*)d_in[6];
    float* out = (float*)d_out;

    cudaFuncSetAttribute(gemm_mma<3, 2>, cudaFuncAttributeMaxDynamicSharedMemorySize, GEMM_SMEM);
    cudaFuncSetAttribute(gemm_mma<1, 4>, cudaFuncAttributeMaxDynamicSharedMemorySize, GEMM_SMEM);

    __nv_bfloat16 *pWgh, *pWgl, *pWsh, *pWsl, *pxh, *pxl, *pLRh, *pLRl;
    float *pSim, *pZ;
    cudaGetSymbolAddress((void**)&pWgh, g_Wgt_h);
    cudaGetSymbolAddress((void**)&pWgl, g_Wgt_l);
    cudaGetSymbolAddress((void**)&pWsh, g_Wst_h);
    cudaGetSymbolAddress((void**)&pWsl, g_Wst_l);
    cudaGetSymbolAddress((void**)&pxh,  g_xh);
    cudaGetSymbolAddress((void**)&pxl,  g_xl);
    cudaGetSymbolAddress((void**)&pLRh, g_LRh);
    cudaGetSymbolAddress((void**)&pLRl, g_LRl);
    cudaGetSymbolAddress((void**)&pSim, g_sim);
    cudaGetSymbolAddress((void**)&pZ,   g_z);

    transpose_split_all<<<dim3(24, 24, 5), dim3(32, 8)>>>(Wg, Ws, pWgh, pWgl, pWsh, pWsl);
    init_x_kernel<<<NUM_L * CC / 256, 256>>>(l_feat, r_feat);

    // GraphGenerator: LR projection, hi-only sim (4-stage), top-16 + rescore
    gemm_mma<3, 2><<<dim3(CC / 128, NTOT / 128), 256, GEMM_SMEM>>>(
        pxh, pxl, pWgh, pWgl, nullptr, pLRh, pLRl, nullptr, nullptr, NTOT, CC, CC, 1);
    gemm_mma<1, 4><<<dim3(NUM_L / 128, NUM_L / 128), 256, GEMM_SMEM>>>(
        pLRh, pLRl, pLRh + (size_t)NUM_L * CC, pLRl + (size_t)NUM_L * CC,
        pSim, nullptr, nullptr, nullptr, nullptr, NUM_L, NUM_L, CC, 0);
    topk_rescore_kernel<<<NUM_L, 256>>>();

    // CSR for graph 1
    zero_deg_kernel<<<16, 256>>>();
    count_deg_kernel<<<NUM_L * KSEL / 256, 256>>>();
    scan_off_kernel<<<1, 512>>>();
    init_cursor_kernel<<<16, 256>>>();
    fill_atomic_kernel<<<NUM_L * KSEL / 256, 256>>>();
    sort_convert_kernel<<<16, 256>>>();

    for (int g = 0; g < 2; g++) {
        for (int l = 0; l < NLAYERS; l++) {
            gemm_mma<3, 2><<<dim3(CC / 128, NTOT / 128), 256, GEMM_SMEM>>>(
                pxh, pxl, pWsh + (size_t)l * CC * CC, pWsl + (size_t)l * CC * CC,
                pZ, nullptr, nullptr,
                a_src + l * HH * DDIM, a_dst + l * HH * DDIM, NTOT, CC, CC, 0);
            int elu = (l < NLAYERS - 1) ? 1 : 0;
            if (g == 0) agg1_kernel<<<NTOT, 256>>>(b + l * CC, elu);
            else        agg2_kernel<<<NTOT, 256>>>(b + l * CC, elu,
                                                   (l == NLAYERS - 1) ? 1 : 0, out);
        }
    }
}